// round 14
// baseline (speedup 1.0000x reference)
#include <cuda_runtime.h>
#include <cuda_bf16.h>
#include <mma.h>
#include <cstdint>

using namespace nvcuda;

// Problem constants (fixed shapes)
#define B_  4
#define H_  160
#define W_  160
#define HW_ (H_ * W_)
#define OC_ 216   // 3 * DG * KK
#define DG_ 8
#define KK_ 9
#define SLOPE_ 0.1f

// ---------------------------------------------------------------------------
// Helpers
// ---------------------------------------------------------------------------
__device__ __forceinline__ void fma2(uint64_t& acc, uint64_t a, uint64_t b) {
    asm("fma.rn.f32x2 %0, %1, %2, %0;" : "+l"(acc) : "l"(a), "l"(b));
}
__device__ __forceinline__ uint64_t dup2(float v) {
    uint64_t d; uint32_t u = __float_as_uint(v);
    asm("mov.b64 %0, {%1, %1};" : "=l"(d) : "r"(u));
    return d;
}
__device__ __forceinline__ void unpk2(uint64_t v, float& lo, float& hi) {
    uint32_t a, b;
    asm("mov.b64 {%0, %1}, %2;" : "=r"(a), "=r"(b) : "l"(v));
    lo = __uint_as_float(a); hi = __uint_as_float(b);
}
__device__ __forceinline__ void cp16(uint32_t s, const void* g) {
    asm volatile("cp.async.cg.shared.global [%0], [%1], 16;" :: "r"(s), "l"(g));
}
#define CP_COMMIT() asm volatile("cp.async.commit_group;")
#define CP_WAIT1()  asm volatile("cp.async.wait_group 1;" ::: "memory")

// ---------------------------------------------------------------------------
// Scratch buffers (static device globals; no runtime allocation allowed)
// ---------------------------------------------------------------------------
__device__ float g_bufA [B_ * HW_ * 64];   // NHWC activations
__device__ float g_bufB [B_ * HW_ * 64];   // NHWC activations
__device__ float g_co   [B_ * OC_ * HW_];  // NCHW offsets/masks
__device__ float g_nbrT [B_ * HW_ * 64];   // NHWC
__device__ float g_refT [B_ * HW_ * 64];   // NHWC
__device__ float g_featT[B_ * HW_ * 64];   // NHWC

// packed bf16 hi/lo weight blobs: [slice][half][tap][{hi,lo}][k=64][NPs]
__device__ __nv_bfloat16 g_wb1[2 * 9 * 2 * 64 * 72];       // conv1 (2 halves)
__device__ __nv_bfloat16 g_wb2[9 * 2 * 64 * 72];           // conv2
__device__ __nv_bfloat16 g_wb3[3 * 9 * 2 * 64 * 88];       // co (3 slices, NP=80)
__device__ __nv_bfloat16 g_wb4[2 * 9 * 2 * 64 * 72];
__device__ __nv_bfloat16 g_wb5[9 * 2 * 64 * 72];
__device__ __nv_bfloat16 g_wb6[3 * 9 * 2 * 64 * 88];

// ---------------------------------------------------------------------------
// NCHW -> NHWC transpose
// ---------------------------------------------------------------------------
__global__ __launch_bounds__(256)
void t_k(const float* __restrict__ in, float* __restrict__ out)
{
    __shared__ float s[64][65];
    const int tid = threadIdx.x;
    const int b = blockIdx.y;
    const int p0 = blockIdx.x * 64;
#pragma unroll 1
    for (int i = tid; i < 64 * 64; i += 256) {
        const int c = i >> 6, p = i & 63;
        s[c][p] = in[((size_t)b * 64 + c) * HW_ + p0 + p];
    }
    __syncthreads();
#pragma unroll 1
    for (int i = tid; i < 64 * 64; i += 256) {
        const int p = i >> 6, c = i & 63;
        out[((size_t)b * HW_ + p0 + p) * 64 + c] = s[c][p];
    }
}

// ---------------------------------------------------------------------------
// Weight packing: w[cout][cin][3][3] fp32 -> [slice][half][tap][{hi,lo}][k][NPs]
// bf16, hi/lo split. n in [nout, np) zero-filled; cols [np, nps) unused.
// ---------------------------------------------------------------------------
__global__ __launch_bounds__(256)
void pack_k(const float* __restrict__ w, int cin_total, int nout, int np,
            int nps, int halves, __nv_bfloat16* __restrict__ blob)
{
    const int slice = blockIdx.y;
    const int cout0 = slice * nout;
    const int taphalf = 64 * nps;
    const int tapsz = 2 * taphalf;
    const int slice_stride = halves * 9 * tapsz;
    const int total = halves * 9 * 64 * np;
#pragma unroll 1
    for (int i = blockIdx.x * 256 + threadIdx.x; i < total; i += gridDim.x * 256) {
        const int n = i % np;
        const int k = (i / np) & 63;
        const int t = (i / (np * 64)) % 9;
        const int h = i / (np * 64 * 9);
        float x = 0.f;
        if (n < nout)
            x = w[((size_t)(cout0 + n) * cin_total + h * 64 + k) * 9 + t];
        const __nv_bfloat16 hi = __float2bfloat16(x);
        const __nv_bfloat16 lo = __float2bfloat16(x - __bfloat162float(hi));
        __nv_bfloat16* dst = blob + (size_t)slice * slice_stride
                             + (h * 9 + t) * tapsz + k * nps + n;
        dst[0] = hi;
        dst[taphalf] = lo;
    }
}

// ---------------------------------------------------------------------------
// wmma bf16 conv3x3 (implicit GEMM, hi/lo 3-pass split), pipelined B stream.
//  Block: 128 px (8 rows x 16 cols), 8 warps; warp w owns px row w (M-tile 16).
//  N = NP (64 or 80 padded from 72), NT = NP/16 n-tiles.
//  Chunk = one {hi|lo} half of one tap's B ([k=64][NPs] bf16). Flat chunk loop
//  with a 3-buffer cp.async ring: wait_group 1 -> sync -> prefetch(ch+2) ->
//  compute(ch). Hi-chunk: D += Ah*B + Al*B ; lo-chunk: D += Ah*B.
//  NOUT==64 -> NHWC fp32 out; NOUT==72 -> NCHW out (3 slices via blockIdx.z).
// ---------------------------------------------------------------------------
template <int NOUT, int NP, int HALVES>
__global__ __launch_bounds__(256, 2)
void tconv_k(const float* __restrict__ in0, const float* __restrict__ in1,
             const __nv_bfloat16* __restrict__ blob,
             const float* __restrict__ bias, float* __restrict__ out, int act)
{
    constexpr int NPs     = NP + 8;
    constexpr int NT      = NP / 16;
    constexpr int CHUNK   = 64 * NPs;            // bf16 elements per chunk
    constexpr int CHUNK_B = CHUNK * 2;           // bytes
    constexpr int B_BYTES = 3 * CHUNK_B;         // ring of 3
    constexpr int A_OFF   = B_BYTES;
    constexpr int A_BYTES = 180 * 72 * 2;        // one bf16 tile (10x18 px, ld 72)
    constexpr int NSLICE  = (NOUT == 72) ? 3 : 1;
    constexpr int LDO     = NP + 4;
    constexpr int CHTOT   = HALVES * 18;

    extern __shared__ uint8_t sm[];
    __nv_bfloat16* smB  = (__nv_bfloat16*)sm;
    __nv_bfloat16* aHiB = (__nv_bfloat16*)(sm + A_OFF);
    __nv_bfloat16* aLoB = (__nv_bfloat16*)(sm + A_OFF + A_BYTES);
    uint32_t* aHi32 = (uint32_t*)aHiB;
    uint32_t* aLo32 = (uint32_t*)aLoB;
    const uint32_t smb = (uint32_t)__cvta_generic_to_shared(sm);

    const int tid  = threadIdx.x;
    const int w    = tid >> 5;
    const int slice = blockIdx.z % NSLICE;
    const int b     = blockIdx.z / NSLICE;
    const int by = blockIdx.y * 8;
    const int bx = blockIdx.x * 16;

    wmma::fragment<wmma::accumulator, 16, 16, 16, float> acc[NT];
#pragma unroll
    for (int nt = 0; nt < NT; ++nt) wmma::fill_fragment(acc[nt], 0.0f);

    const __nv_bfloat16* bl = blob + (size_t)slice * (HALVES * 9 * 2 * CHUNK);

    // ---- A staging: NHWC fp32 -> bf16 hi/lo (halo 10x18, ld 72) ----
    auto stageA = [&](int h) {
        const float* src = ((HALVES == 2 && h == 1) ? in1 : in0) + (size_t)b * HW_ * 64;
#pragma unroll 1
        for (int i = tid; i < 180 * 32; i += 256) {
            const int pix = i >> 5;        // pr*18 + pc
            const int j   = i & 31;        // channel pair
            const int pr  = pix / 18, pc = pix - pr * 18;
            const int gy = by + pr - 1, gx = bx + pc - 1;
            float2 v = make_float2(0.f, 0.f);
            if (gy >= 0 && gy < H_ && gx >= 0 && gx < W_)
                v = *(const float2*)(src + ((size_t)(gy * W_ + gx)) * 64 + 2 * j);
            const __nv_bfloat16 h0 = __float2bfloat16(v.x);
            const __nv_bfloat16 h1 = __float2bfloat16(v.y);
            const __nv_bfloat16 l0 = __float2bfloat16(v.x - __bfloat162float(h0));
            const __nv_bfloat16 l1 = __float2bfloat16(v.y - __bfloat162float(h1));
            aHi32[pix * 36 + j] = (uint32_t)__bfloat16_as_ushort(h0) |
                                  ((uint32_t)__bfloat16_as_ushort(h1) << 16);
            aLo32[pix * 36 + j] = (uint32_t)__bfloat16_as_ushort(l0) |
                                  ((uint32_t)__bfloat16_as_ushort(l1) << 16);
        }
    };

    // ---- B chunk prefetch into ring ----
    auto prefetchB = [&](int ch) {
        const int tg = ch >> 1;            // global tap
        const int hl = ch & 1;             // 0 = hi, 1 = lo
        const __nv_bfloat16* src = bl + (size_t)tg * (2 * CHUNK) + hl * CHUNK;
        const uint32_t dst = smb + (uint32_t)((ch % 3) * CHUNK_B);
#pragma unroll 1
        for (int i = tid * 16; i < CHUNK_B; i += 256 * 16)
            cp16(dst + i, (const uint8_t*)src + i);
    };

    stageA(0);
    prefetchB(0); CP_COMMIT();
    prefetchB(1); CP_COMMIT();

#pragma unroll 1
    for (int ch = 0; ch < CHTOT; ++ch) {
        CP_WAIT1();            // chunk ch's copy complete (<=1 group pending)
        __syncthreads();       // all warps done with compute(ch-1); A visible
        if (HALVES == 2 && ch == 18) {
            stageA(1);         // safe: compute(0..17) done by all warps
            __syncthreads();
        }
        if (ch + 2 < CHTOT) prefetchB(ch + 2);
        CP_COMMIT();           // unconditional: keeps group accounting uniform

        const int t  = (ch >> 1) % 9;
        const int hl = ch & 1;
        const int ky = t / 3, kx = t - ky * 3;
        const __nv_bfloat16* bc = smB + (ch % 3) * CHUNK;
        const int abase = ((w + ky) * 18 + kx) * 72;

#pragma unroll
        for (int kc = 0; kc < 4; ++kc) {
            wmma::fragment<wmma::matrix_a, 16, 16, 16, __nv_bfloat16,
                           wmma::row_major> fa_h, fa_l;
            wmma::load_matrix_sync(fa_h, aHiB + abase + kc * 16, 72);
            if (hl == 0)
                wmma::load_matrix_sync(fa_l, aLoB + abase + kc * 16, 72);
#pragma unroll
            for (int nt = 0; nt < NT; ++nt) {
                wmma::fragment<wmma::matrix_b, 16, 16, 16, __nv_bfloat16,
                               wmma::row_major> fb;
                wmma::load_matrix_sync(fb, bc + kc * 16 * NPs + nt * 16, NPs);
                wmma::mma_sync(acc[nt], fa_h, fb, acc[nt]);
                if (hl == 0)
                    wmma::mma_sync(acc[nt], fa_l, fb, acc[nt]);
            }
        }
    }

    // ---- epilogue ----
    __syncthreads();
    float* smf = (float*)(sm + A_OFF);   // reuse A region
#pragma unroll
    for (int nt = 0; nt < NT; ++nt)
        wmma::store_matrix_sync(smf + w * 16 * LDO + nt * 16, acc[nt], LDO,
                                wmma::mem_row_major);
    __syncthreads();

    if (NOUT == 64) {
#pragma unroll 1
        for (int i = tid; i < 128 * 16; i += 256) {
            const int c4 = i & 15;
            const int p  = i >> 4;
            float4 v = *(float4*)(smf + p * LDO + 4 * c4);
            v.x += bias[4 * c4];
            v.y += bias[4 * c4 + 1];
            v.z += bias[4 * c4 + 2];
            v.w += bias[4 * c4 + 3];
            if (act) {
                v.x = (v.x > 0.f) ? v.x : SLOPE_ * v.x;
                v.y = (v.y > 0.f) ? v.y : SLOPE_ * v.y;
                v.z = (v.z > 0.f) ? v.z : SLOPE_ * v.z;
                v.w = (v.w > 0.f) ? v.w : SLOPE_ * v.w;
            }
            const int py = by + (p >> 4);
            const int px = bx + (p & 15);
            *(float4*)(out + ((size_t)b * HW_ + py * W_ + px) * 64 + 4 * c4) = v;
        }
    } else {
        const float* bs = bias + slice * NOUT;
#pragma unroll 1
        for (int i = tid; i < NOUT * 128; i += 256) {
            const int c = i >> 7;
            const int p = i & 127;
            float v = smf[p * LDO + c] + bs[c];
            if (act) v = (v > 0.f) ? v : SLOPE_ * v;
            const int py = by + (p >> 4);
            const int px = bx + (p & 15);
            out[((size_t)b * OC_ + slice * NOUT + c) * HW_ + py * W_ + px] = v;
        }
    }
}

// ---------------------------------------------------------------------------
// Modulated deformable conv (DCNv2Pack apply) — NHWC gathers + FFMA2.
// (unchanged from passing R11 version)
// ---------------------------------------------------------------------------
__global__ __launch_bounds__(256, 2)
void dcn_k(const float* __restrict__ xT, const float* __restrict__ co,
           const float* __restrict__ wgt, const float* __restrict__ bias,
           float* __restrict__ out, float* __restrict__ outT, int act)
{
    __shared__ float s_wg[KK_ * 8 * 64];

    const int tid = threadIdx.x;
    const int b   = blockIdx.z;
    const int y   = blockIdx.y * 16 + (tid >> 4);
    const int x   = blockIdx.x * 16 + (tid & 15);

    uint64_t acc2[32];
#pragma unroll
    for (int j = 0; j < 32; ++j) acc2[j] = 0ull;

    const float* cob = co + (size_t)b * OC_ * HW_;
    const float* xb  = xT + (size_t)b * HW_ * 64;
    const int pix = y * W_ + x;

#pragma unroll 1
    for (int g = 0; g < DG_; ++g) {
        __syncthreads();
#pragma unroll 1
        for (int i = tid; i < KK_ * 8 * 64; i += 256) {
            const int o = i & 63;
            const int r = i >> 6;
            const int k = r >> 3;
            const int c = r & 7;
            s_wg[i] = wgt[((size_t)o * 64 + g * 8 + c) * KK_ + k];
        }
        __syncthreads();

#pragma unroll 1
        for (int k = 0; k < KK_; ++k) {
            const float offy = cob[(size_t)(g * 18 + 2 * k    ) * HW_ + pix];
            const float offx = cob[(size_t)(g * 18 + 2 * k + 1) * HW_ + pix];
            const float ml   = cob[(size_t)(144 + g * 9 + k   ) * HW_ + pix];
            const float m    = 1.f / (1.f + __expf(-ml));

            const float py = (float)y + (float)(k / 3 - 1) + offy;
            const float px = (float)x + (float)(k % 3 - 1) + offx;
            const float y0f = floorf(py), x0f = floorf(px);
            const float ly = py - y0f,  lx = px - x0f;
            const int y0 = (int)y0f,    x0 = (int)x0f;

            const float w00 = (1.f - ly) * (1.f - lx) * m;
            const float w01 = (1.f - ly) * lx * m;
            const float w10 = ly * (1.f - lx) * m;
            const float w11 = ly * lx * m;

            const bool iy0 = (y0 >= 0)     && (y0 < H_);
            const bool iy1 = (y0 + 1 >= 0) && (y0 + 1 < H_);
            const bool ix0 = (x0 >= 0)     && (x0 < W_);
            const bool ix1 = (x0 + 1 >= 0) && (x0 + 1 < W_);

            float4 c00a = {0,0,0,0}, c00b = {0,0,0,0};
            float4 c01a = {0,0,0,0}, c01b = {0,0,0,0};
            float4 c10a = {0,0,0,0}, c10b = {0,0,0,0};
            float4 c11a = {0,0,0,0}, c11b = {0,0,0,0};
            if (iy0 && ix0) {
                const float4* p = (const float4*)(xb + ((size_t)(y0 * W_ + x0)) * 64 + g * 8);
                c00a = __ldg(p); c00b = __ldg(p + 1);
            }
            if (iy0 && ix1) {
                const float4* p = (const float4*)(xb + ((size_t)(y0 * W_ + x0 + 1)) * 64 + g * 8);
                c01a = __ldg(p); c01b = __ldg(p + 1);
            }
            if (iy1 && ix0) {
                const float4* p = (const float4*)(xb + ((size_t)((y0 + 1) * W_ + x0)) * 64 + g * 8);
                c10a = __ldg(p); c10b = __ldg(p + 1);
            }
            if (iy1 && ix1) {
                const float4* p = (const float4*)(xb + ((size_t)((y0 + 1) * W_ + x0 + 1)) * 64 + g * 8);
                c11a = __ldg(p); c11b = __ldg(p + 1);
            }

            float s[8];
            s[0] = w00*c00a.x + w01*c01a.x + w10*c10a.x + w11*c11a.x;
            s[1] = w00*c00a.y + w01*c01a.y + w10*c10a.y + w11*c11a.y;
            s[2] = w00*c00a.z + w01*c01a.z + w10*c10a.z + w11*c11a.z;
            s[3] = w00*c00a.w + w01*c01a.w + w10*c10a.w + w11*c11a.w;
            s[4] = w00*c00b.x + w01*c01b.x + w10*c10b.x + w11*c11b.x;
            s[5] = w00*c00b.y + w01*c01b.y + w10*c10b.y + w11*c11b.y;
            s[6] = w00*c00b.z + w01*c01b.z + w10*c10b.z + w11*c11b.z;
            s[7] = w00*c00b.w + w01*c01b.w + w10*c10b.w + w11*c11b.w;

#pragma unroll
            for (int c = 0; c < 8; ++c) {
                const uint64_t s2 = dup2(s[c]);
                const ulonglong2* wr =
                    reinterpret_cast<const ulonglong2*>(&s_wg[(k * 8 + c) * 64]);
#pragma unroll
                for (int q = 0; q < 16; ++q) {
                    const ulonglong2 w4 = wr[q];
                    fma2(acc2[2 * q    ], s2, w4.x);
                    fma2(acc2[2 * q + 1], s2, w4.y);
                }
            }
        }
    }

    float v[64];
#pragma unroll
    for (int j = 0; j < 32; ++j) {
        float v0, v1;
        unpk2(acc2[j], v0, v1);
        v0 += bias[2 * j];
        v1 += bias[2 * j + 1];
        if (act) {
            v0 = (v0 > 0.f) ? v0 : SLOPE_ * v0;
            v1 = (v1 > 0.f) ? v1 : SLOPE_ * v1;
        }
        v[2 * j] = v0; v[2 * j + 1] = v1;
    }
    if (out) {
#pragma unroll
        for (int o = 0; o < 64; ++o)
            out[(((size_t)b * 64 + o) * H_ + y) * W_ + x] = v[o];
    }
    if (outT) {
        float4* dst = (float4*)(outT + ((size_t)b * HW_ + pix) * 64);
#pragma unroll
        for (int q = 0; q < 16; ++q)
            dst[q] = make_float4(v[4*q], v[4*q+1], v[4*q+2], v[4*q+3]);
    }
}

// ---------------------------------------------------------------------------
// Launch
// ---------------------------------------------------------------------------
extern "C" void kernel_launch(void* const* d_in, const int* in_sizes, int n_in,
                              void* d_out, int out_size)
{
    const float* nbr     = (const float*)d_in[0];
    const float* ref     = (const float*)d_in[1];
    const float* w_off1  = (const float*)d_in[2];
    const float* b_off1  = (const float*)d_in[3];
    const float* w_off2  = (const float*)d_in[4];
    const float* b_off2  = (const float*)d_in[5];
    const float* w_co    = (const float*)d_in[6];
    const float* b_co    = (const float*)d_in[7];
    const float* w_dcn   = (const float*)d_in[8];
    const float* b_dcn   = (const float*)d_in[9];
    const float* w_coff1 = (const float*)d_in[10];
    const float* b_coff1 = (const float*)d_in[11];
    const float* w_coff2 = (const float*)d_in[12];
    const float* b_coff2 = (const float*)d_in[13];
    const float* w_cco   = (const float*)d_in[14];
    const float* b_cco   = (const float*)d_in[15];
    const float* w_cdcn  = (const float*)d_in[16];
    const float* b_cdcn  = (const float*)d_in[17];
    float* outp = (float*)d_out;

    void *pA, *pB, *pCO, *pNT, *pRT, *pFT;
    void *pw1, *pw2, *pw3, *pw4, *pw5, *pw6;
    cudaGetSymbolAddress(&pA,  g_bufA);
    cudaGetSymbolAddress(&pB,  g_bufB);
    cudaGetSymbolAddress(&pCO, g_co);
    cudaGetSymbolAddress(&pNT, g_nbrT);
    cudaGetSymbolAddress(&pRT, g_refT);
    cudaGetSymbolAddress(&pFT, g_featT);
    cudaGetSymbolAddress(&pw1, g_wb1);
    cudaGetSymbolAddress(&pw2, g_wb2);
    cudaGetSymbolAddress(&pw3, g_wb3);
    cudaGetSymbolAddress(&pw4, g_wb4);
    cudaGetSymbolAddress(&pw5, g_wb5);
    cudaGetSymbolAddress(&pw6, g_wb6);
    float* bufA  = (float*)pA;
    float* bufB  = (float*)pB;
    float* bufCO = (float*)pCO;
    float* nbrT  = (float*)pNT;
    float* refT  = (float*)pRT;
    float* featT = (float*)pFT;

    // dynamic smem: 3-chunk B ring + 2 A tiles
    constexpr int SM64 = 3 * 64 * 72 * 2 + 2 * 180 * 72 * 2;   // 27648+51840=79488
    constexpr int SM80 = 3 * 64 * 88 * 2 + 2 * 180 * 72 * 2;   // 33792+51840=85632
    cudaFuncSetAttribute(tconv_k<64, 64, 2>, cudaFuncAttributeMaxDynamicSharedMemorySize, SM64);
    cudaFuncSetAttribute(tconv_k<64, 64, 1>, cudaFuncAttributeMaxDynamicSharedMemorySize, SM64);
    cudaFuncSetAttribute(tconv_k<72, 80, 1>, cudaFuncAttributeMaxDynamicSharedMemorySize, SM80);

    const dim3 blk(256);
    const dim3 gT(HW_ / 64, B_);
    const dim3 gC(W_ / 16, H_ / 8, B_);          // (10, 20, 4)
    const dim3 gC3(W_ / 16, H_ / 8, B_ * 3);     // (10, 20, 12)
    const dim3 gD(W_ / 16, H_ / 16, B_);

    // transposes
    t_k<<<gT, blk>>>(nbr, nbrT);
    t_k<<<gT, blk>>>(ref, refT);

    // weight packing
    pack_k<<<dim3(72, 1), blk>>>(w_off1, 128, 64, 64, 72, 2, (__nv_bfloat16*)pw1);
    pack_k<<<dim3(36, 1), blk>>>(w_off2,  64, 64, 64, 72, 1, (__nv_bfloat16*)pw2);
    pack_k<<<dim3(18, 3), blk>>>(w_co,    64, 72, 80, 88, 1, (__nv_bfloat16*)pw3);
    pack_k<<<dim3(72, 1), blk>>>(w_coff1, 128, 64, 64, 72, 2, (__nv_bfloat16*)pw4);
    pack_k<<<dim3(36, 1), blk>>>(w_coff2,  64, 64, 64, 72, 1, (__nv_bfloat16*)pw5);
    pack_k<<<dim3(18, 3), blk>>>(w_cco,    64, 72, 80, 88, 1, (__nv_bfloat16*)pw6);

    // ---- first alignment stage ----
    tconv_k<64, 64, 2><<<gC, blk, SM64>>>(nbrT, refT, (__nv_bfloat16*)pw1, b_off1, bufA, 1);
    tconv_k<64, 64, 1><<<gC, blk, SM64>>>(bufA, nullptr, (__nv_bfloat16*)pw2, b_off2, bufB, 1);
    tconv_k<72, 80, 1><<<gC3, blk, SM80>>>(bufB, nullptr, (__nv_bfloat16*)pw3, b_co, bufCO, 0);
    dcn_k<<<gD, blk>>>(nbrT, bufCO, w_dcn, b_dcn, nullptr, featT, 1);

    // ---- cascade stage ----
    tconv_k<64, 64, 2><<<gC, blk, SM64>>>(featT, refT, (__nv_bfloat16*)pw4, b_coff1, bufA, 1);
    tconv_k<64, 64, 1><<<gC, blk, SM64>>>(bufA, nullptr, (__nv_bfloat16*)pw5, b_coff2, bufB, 1);
    tconv_k<72, 80, 1><<<gC3, blk, SM80>>>(bufB, nullptr, (__nv_bfloat16*)pw6, b_cco, bufCO, 0);
    dcn_k<<<gD, blk>>>(featT, bufCO, w_cdcn, b_cdcn, outp, nullptr, 1);
}

// round 15
// speedup vs baseline: 1.2324x; 1.2324x over previous
#include <cuda_runtime.h>
#include <cuda_bf16.h>
#include <mma.h>
#include <cstdint>

using namespace nvcuda;

// Problem constants (fixed shapes)
#define B_  4
#define H_  160
#define W_  160
#define HW_ (H_ * W_)
#define OC_ 216   // 3 * DG * KK
#define DG_ 8
#define KK_ 9
#define SLOPE_ 0.1f

// ---------------------------------------------------------------------------
// Helpers
// ---------------------------------------------------------------------------
__device__ __forceinline__ void cp16(uint32_t s, const void* g) {
    asm volatile("cp.async.cg.shared.global [%0], [%1], 16;" :: "r"(s), "l"(g));
}
#define CP_COMMIT() asm volatile("cp.async.commit_group;")
#define CP_WAIT0()  asm volatile("cp.async.wait_group 0;" ::: "memory")
#define CP_WAIT1()  asm volatile("cp.async.wait_group 1;" ::: "memory")

// ---------------------------------------------------------------------------
// Scratch buffers (static device globals; no runtime allocation allowed)
// ---------------------------------------------------------------------------
__device__ float g_bufA [B_ * HW_ * 64];   // NHWC activations
__device__ float g_bufB [B_ * HW_ * 64];   // NHWC activations
__device__ float g_co   [B_ * OC_ * HW_];  // NCHW offsets/masks
__device__ float g_nbrT [B_ * HW_ * 64];   // NHWC
__device__ float g_refT [B_ * HW_ * 64];   // NHWC
__device__ float g_featT[B_ * HW_ * 64];   // NHWC

// packed bf16 hi/lo weight blobs: [slice][half][tap][{hi,lo}][k=64][NPs]
__device__ __nv_bfloat16 g_wb1[2 * 9 * 2 * 64 * 72];       // conv1 (2 halves)
__device__ __nv_bfloat16 g_wb2[9 * 2 * 64 * 72];           // conv2
__device__ __nv_bfloat16 g_wb3[3 * 9 * 2 * 64 * 88];       // co (3 slices, NP=80)
__device__ __nv_bfloat16 g_wb4[2 * 9 * 2 * 64 * 72];
__device__ __nv_bfloat16 g_wb5[9 * 2 * 64 * 72];
__device__ __nv_bfloat16 g_wb6[3 * 9 * 2 * 64 * 88];

// packed dcn weight blobs: [g][{hi,lo}][k'=80][n=72]  (k' = tap*8 + c)
#define DBG_ (80 * 72)
__device__ __nv_bfloat16 g_wd1[DG_ * 2 * DBG_];
__device__ __nv_bfloat16 g_wd2[DG_ * 2 * DBG_];

// ---------------------------------------------------------------------------
// NCHW -> NHWC transpose
// ---------------------------------------------------------------------------
__global__ __launch_bounds__(256)
void t_k(const float* __restrict__ in, float* __restrict__ out)
{
    __shared__ float s[64][65];
    const int tid = threadIdx.x;
    const int b = blockIdx.y;
    const int p0 = blockIdx.x * 64;
#pragma unroll 1
    for (int i = tid; i < 64 * 64; i += 256) {
        const int c = i >> 6, p = i & 63;
        s[c][p] = in[((size_t)b * 64 + c) * HW_ + p0 + p];
    }
    __syncthreads();
#pragma unroll 1
    for (int i = tid; i < 64 * 64; i += 256) {
        const int p = i >> 6, c = i & 63;
        out[((size_t)b * HW_ + p0 + p) * 64 + c] = s[c][p];
    }
}

// ---------------------------------------------------------------------------
// Conv weight packing (unchanged from R11)
// ---------------------------------------------------------------------------
__global__ __launch_bounds__(256)
void pack_k(const float* __restrict__ w, int cin_total, int nout, int np,
            int nps, int halves, __nv_bfloat16* __restrict__ blob)
{
    const int slice = blockIdx.y;
    const int cout0 = slice * nout;
    const int taphalf = 64 * nps;
    const int tapsz = 2 * taphalf;
    const int slice_stride = halves * 9 * tapsz;
    const int total = halves * 9 * 64 * np;
#pragma unroll 1
    for (int i = blockIdx.x * 256 + threadIdx.x; i < total; i += gridDim.x * 256) {
        const int n = i % np;
        const int k = (i / np) & 63;
        const int t = (i / (np * 64)) % 9;
        const int h = i / (np * 64 * 9);
        float x = 0.f;
        if (n < nout)
            x = w[((size_t)(cout0 + n) * cin_total + h * 64 + k) * 9 + t];
        const __nv_bfloat16 hi = __float2bfloat16(x);
        const __nv_bfloat16 lo = __float2bfloat16(x - __bfloat162float(hi));
        __nv_bfloat16* dst = blob + (size_t)slice * slice_stride
                             + (h * 9 + t) * tapsz + k * nps + n;
        dst[0] = hi;
        dst[taphalf] = lo;
    }
}

// ---------------------------------------------------------------------------
// DCN weight packing: w[o=64][cin=64][3][3] -> [g][{hi,lo}][k'=80][72]
//   k' = tap*8 + c (c = channel within group), col n = o; pads zero-filled.
// ---------------------------------------------------------------------------
__global__ __launch_bounds__(256)
void pack_dcn(const float* __restrict__ w, __nv_bfloat16* __restrict__ blob)
{
    const int total = DG_ * 80 * 72;
#pragma unroll 1
    for (int i = blockIdx.x * 256 + threadIdx.x; i < total; i += gridDim.x * 256) {
        const int n = i % 72;
        const int k = (i / 72) % 80;
        const int g = i / (72 * 80);
        float x = 0.f;
        if (n < 64 && k < 72)
            x = w[((size_t)n * 64 + g * 8 + (k & 7)) * 9 + (k >> 3)];
        const __nv_bfloat16 hi = __float2bfloat16(x);
        const __nv_bfloat16 lo = __float2bfloat16(x - __bfloat162float(hi));
        blob[(size_t)g * 2 * DBG_ + k * 72 + n]        = hi;
        blob[(size_t)g * 2 * DBG_ + DBG_ + k * 72 + n] = lo;
    }
}

// ---------------------------------------------------------------------------
// wmma bf16 conv3x3 — EXACT R11 version (measured 2494us total).
// ---------------------------------------------------------------------------
template <int NOUT, int NP, int HALVES>
__global__ __launch_bounds__(256, 2)
void tconv_k(const float* __restrict__ in0, const float* __restrict__ in1,
             const __nv_bfloat16* __restrict__ blob,
             const float* __restrict__ bias, float* __restrict__ out, int act)
{
    constexpr int NPs     = NP + 8;
    constexpr int NT      = NP / 16;
    constexpr int TAPHALF = 64 * NPs;
    constexpr int TAPSZ   = 2 * TAPHALF;
    constexpr int B_BYTES = TAPSZ * 2;
    constexpr int A_OFF   = B_BYTES;
    constexpr int A_BYTES = 180 * 72 * 2;
    constexpr int NSLICE  = (NOUT == 72) ? 3 : 1;
    constexpr int LDO     = NP + 4;

    extern __shared__ uint8_t sm[];
    __nv_bfloat16* smB  = (__nv_bfloat16*)sm;
    __nv_bfloat16* aHiB = (__nv_bfloat16*)(sm + A_OFF);
    __nv_bfloat16* aLoB = (__nv_bfloat16*)(sm + A_OFF + A_BYTES);
    uint32_t* aHi32 = (uint32_t*)aHiB;
    uint32_t* aLo32 = (uint32_t*)aLoB;
    const uint32_t smb = (uint32_t)__cvta_generic_to_shared(sm);

    const int tid  = threadIdx.x;
    const int w    = tid >> 5;
    const int slice = blockIdx.z % NSLICE;
    const int b     = blockIdx.z / NSLICE;
    const int by = blockIdx.y * 8;
    const int bx = blockIdx.x * 16;

    wmma::fragment<wmma::accumulator, 16, 16, 16, float> acc[NT];
#pragma unroll
    for (int nt = 0; nt < NT; ++nt) wmma::fill_fragment(acc[nt], 0.0f);

    const __nv_bfloat16* bl = blob + (size_t)slice * (HALVES * 9 * TAPSZ);

#pragma unroll 1
    for (int h = 0; h < HALVES; ++h) {
        __syncthreads();

        const float* src = ((HALVES == 2 && h == 1) ? in1 : in0) + (size_t)b * HW_ * 64;
#pragma unroll 1
        for (int i = tid; i < 180 * 32; i += 256) {
            const int pix = i >> 5;
            const int j   = i & 31;
            const int pr  = pix / 18, pc = pix - pr * 18;
            const int gy = by + pr - 1, gx = bx + pc - 1;
            float2 v = make_float2(0.f, 0.f);
            if (gy >= 0 && gy < H_ && gx >= 0 && gx < W_)
                v = *(const float2*)(src + ((size_t)(gy * W_ + gx)) * 64 + 2 * j);
            const __nv_bfloat16 h0 = __float2bfloat16(v.x);
            const __nv_bfloat16 h1 = __float2bfloat16(v.y);
            const __nv_bfloat16 l0 = __float2bfloat16(v.x - __bfloat162float(h0));
            const __nv_bfloat16 l1 = __float2bfloat16(v.y - __bfloat162float(h1));
            aHi32[pix * 36 + j] = (uint32_t)__bfloat16_as_ushort(h0) |
                                  ((uint32_t)__bfloat16_as_ushort(h1) << 16);
            aLo32[pix * 36 + j] = (uint32_t)__bfloat16_as_ushort(l0) |
                                  ((uint32_t)__bfloat16_as_ushort(l1) << 16);
        }

#pragma unroll 1
        for (int t = 0; t < 9; ++t) {
            __syncthreads();
            const __nv_bfloat16* bsrc = bl + (size_t)(h * 9 + t) * TAPSZ;
#pragma unroll 1
            for (int i = tid * 16; i < B_BYTES; i += 256 * 16)
                cp16(smb + i, (const uint8_t*)bsrc + i);
            CP_COMMIT();
            CP_WAIT0();
            __syncthreads();

            const int ky = t / 3, kx = t - ky * 3;
            const int abase0 = ((w + ky) * 18 + kx) * 72;
#pragma unroll
            for (int kc = 0; kc < 4; ++kc) {
                wmma::fragment<wmma::matrix_a, 16, 16, 16, __nv_bfloat16,
                               wmma::row_major> fa_h, fa_l;
                wmma::load_matrix_sync(fa_h, aHiB + abase0 + kc * 16, 72);
                wmma::load_matrix_sync(fa_l, aLoB + abase0 + kc * 16, 72);
#pragma unroll
                for (int nt = 0; nt < NT; ++nt) {
                    wmma::fragment<wmma::matrix_b, 16, 16, 16, __nv_bfloat16,
                                   wmma::row_major> fb;
                    wmma::load_matrix_sync(fb, smB + kc * 16 * NPs + nt * 16, NPs);
                    wmma::mma_sync(acc[nt], fa_h, fb, acc[nt]);
                    wmma::mma_sync(acc[nt], fa_l, fb, acc[nt]);
                    wmma::load_matrix_sync(fb, smB + TAPHALF + kc * 16 * NPs + nt * 16, NPs);
                    wmma::mma_sync(acc[nt], fa_h, fb, acc[nt]);
                }
            }
        }
    }

    __syncthreads();
    float* smf = (float*)(sm + A_OFF);
#pragma unroll
    for (int nt = 0; nt < NT; ++nt)
        wmma::store_matrix_sync(smf + w * 16 * LDO + nt * 16, acc[nt], LDO,
                                wmma::mem_row_major);
    __syncthreads();

    if (NOUT == 64) {
#pragma unroll 1
        for (int i = tid; i < 128 * 16; i += 256) {
            const int c4 = i & 15;
            const int p  = i >> 4;
            float4 v = *(float4*)(smf + p * LDO + 4 * c4);
            v.x += bias[4 * c4];
            v.y += bias[4 * c4 + 1];
            v.z += bias[4 * c4 + 2];
            v.w += bias[4 * c4 + 3];
            if (act) {
                v.x = (v.x > 0.f) ? v.x : SLOPE_ * v.x;
                v.y = (v.y > 0.f) ? v.y : SLOPE_ * v.y;
                v.z = (v.z > 0.f) ? v.z : SLOPE_ * v.z;
                v.w = (v.w > 0.f) ? v.w : SLOPE_ * v.w;
            }
            const int py = by + (p >> 4);
            const int px = bx + (p & 15);
            *(float4*)(out + ((size_t)b * HW_ + py * W_ + px) * 64 + 4 * c4) = v;
        }
    } else {
        const float* bs = bias + slice * NOUT;
#pragma unroll 1
        for (int i = tid; i < NOUT * 128; i += 256) {
            const int c = i >> 7;
            const int p = i & 127;
            float v = smf[p * LDO + c] + bs[c];
            if (act) v = (v > 0.f) ? v : SLOPE_ * v;
            const int py = by + (p >> 4);
            const int px = bx + (p & 15);
            out[((size_t)b * OC_ + slice * NOUT + c) * HW_ + py * W_ + px] = v;
        }
    }
}

// ---------------------------------------------------------------------------
// DCN with wmma contraction.
//  Block: 128 px (8 rows x 16 cols), 8 warps; warp w = M-tile (16 px).
//  Per group g: gather 9 taps x 8 ch bilinear+mask samples -> smem A panel
//  [128][88] bf16 hi/lo (K' = tap*8+c, padded 72->80), then 3-pass wmma
//  against per-group packed B [80][72] (hi/lo), accumulating over 8 groups.
//  B staged via cp.async ring of 2 (23040 B/group).
// ---------------------------------------------------------------------------
__global__ __launch_bounds__(256, 2)
void dcnw_k(const float* __restrict__ xT, const float* __restrict__ co,
            const __nv_bfloat16* __restrict__ wblob,
            const float* __restrict__ bias,
            float* __restrict__ out, float* __restrict__ outT, int act)
{
    constexpr int CH_B  = 2 * DBG_ * 2;       // bytes per group chunk (hi+lo)
    constexpr int A_OFF = 2 * CH_B;           // ring of 2
    constexpr int A_ELE = 128 * 88;

    extern __shared__ uint8_t sm[];
    __nv_bfloat16* smB = (__nv_bfloat16*)sm;
    __nv_bfloat16* aHi = (__nv_bfloat16*)(sm + A_OFF);
    __nv_bfloat16* aLo = aHi + A_ELE;
    const uint32_t smb = (uint32_t)__cvta_generic_to_shared(sm);

    const int tid = threadIdx.x;
    const int w   = tid >> 5;
    const int b   = blockIdx.z;
    const int by  = blockIdx.y * 8;
    const int bx  = blockIdx.x * 16;

    const float* cob = co + (size_t)b * OC_ * HW_;
    const float* xb  = xT + (size_t)b * HW_ * 64;

    // zero K-pad columns (72..79) once; region untouched by gathers
    {
        const int row = tid & 127;
        __nv_bfloat16* dst = ((tid < 128) ? aHi : aLo) + row * 88 + 72;
        *(uint4*)dst = make_uint4(0, 0, 0, 0);
    }

    wmma::fragment<wmma::accumulator, 16, 16, 16, float> acc[4];
#pragma unroll
    for (int nt = 0; nt < 4; ++nt) wmma::fill_fragment(acc[nt], 0.0f);

    auto prefetchB = [&](int g) {
        const uint8_t* src = (const uint8_t*)(wblob + (size_t)g * 2 * DBG_);
        const uint32_t dst = smb + (uint32_t)((g & 1) * CH_B);
#pragma unroll 1
        for (int i = tid * 16; i < CH_B; i += 256 * 16)
            cp16(dst + i, src + i);
    };
    prefetchB(0); CP_COMMIT();

#pragma unroll 1
    for (int g = 0; g < DG_; ++g) {
        __syncthreads();                 // compute(g-1) done: A + B(g-1) free
        if (g + 1 < DG_) prefetchB(g + 1);
        CP_COMMIT();

        // ---- gather A panel for group g ----
#pragma unroll 1
        for (int i = tid; i < 128 * 9; i += 256) {
            const int px = i & 127;
            const int k  = i >> 7;       // tap 0..8
            const int y = by + (px >> 4);
            const int x = bx + (px & 15);
            const int pix = y * W_ + x;

            const float offy = cob[(size_t)(g * 18 + 2 * k    ) * HW_ + pix];
            const float offx = cob[(size_t)(g * 18 + 2 * k + 1) * HW_ + pix];
            const float ml   = cob[(size_t)(144 + g * 9 + k   ) * HW_ + pix];
            const float m    = 1.f / (1.f + __expf(-ml));

            const float py = (float)y + (float)(k / 3 - 1) + offy;
            const float pxf = (float)x + (float)(k % 3 - 1) + offx;
            const float y0f = floorf(py), x0f = floorf(pxf);
            const float ly = py - y0f,  lx = pxf - x0f;
            const int y0 = (int)y0f,    x0 = (int)x0f;

            const float w00 = (1.f - ly) * (1.f - lx) * m;
            const float w01 = (1.f - ly) * lx * m;
            const float w10 = ly * (1.f - lx) * m;
            const float w11 = ly * lx * m;

            const bool iy0 = (y0 >= 0)     && (y0 < H_);
            const bool iy1 = (y0 + 1 >= 0) && (y0 + 1 < H_);
            const bool ix0 = (x0 >= 0)     && (x0 < W_);
            const bool ix1 = (x0 + 1 >= 0) && (x0 + 1 < W_);

            float4 c00a = {0,0,0,0}, c00b = {0,0,0,0};
            float4 c01a = {0,0,0,0}, c01b = {0,0,0,0};
            float4 c10a = {0,0,0,0}, c10b = {0,0,0,0};
            float4 c11a = {0,0,0,0}, c11b = {0,0,0,0};
            if (iy0 && ix0) {
                const float4* p = (const float4*)(xb + ((size_t)(y0 * W_ + x0)) * 64 + g * 8);
                c00a = __ldg(p); c00b = __ldg(p + 1);
            }
            if (iy0 && ix1) {
                const float4* p = (const float4*)(xb + ((size_t)(y0 * W_ + x0 + 1)) * 64 + g * 8);
                c01a = __ldg(p); c01b = __ldg(p + 1);
            }
            if (iy1 && ix0) {
                const float4* p = (const float4*)(xb + ((size_t)((y0 + 1) * W_ + x0)) * 64 + g * 8);
                c10a = __ldg(p); c10b = __ldg(p + 1);
            }
            if (iy1 && ix1) {
                const float4* p = (const float4*)(xb + ((size_t)((y0 + 1) * W_ + x0 + 1)) * 64 + g * 8);
                c11a = __ldg(p); c11b = __ldg(p + 1);
            }

            float s[8];
            s[0] = w00*c00a.x + w01*c01a.x + w10*c10a.x + w11*c11a.x;
            s[1] = w00*c00a.y + w01*c01a.y + w10*c10a.y + w11*c11a.y;
            s[2] = w00*c00a.z + w01*c01a.z + w10*c10a.z + w11*c11a.z;
            s[3] = w00*c00a.w + w01*c01a.w + w10*c10a.w + w11*c11a.w;
            s[4] = w00*c00b.x + w01*c01b.x + w10*c10b.x + w11*c11b.x;
            s[5] = w00*c00b.y + w01*c01b.y + w10*c10b.y + w11*c11b.y;
            s[6] = w00*c00b.z + w01*c01b.z + w10*c10b.z + w11*c11b.z;
            s[7] = w00*c00b.w + w01*c01b.w + w10*c10b.w + w11*c11b.w;

            __nv_bfloat16 hi8[8], lo8[8];
#pragma unroll
            for (int c = 0; c < 8; ++c) {
                hi8[c] = __float2bfloat16(s[c]);
                lo8[c] = __float2bfloat16(s[c] - __bfloat162float(hi8[c]));
            }
            *(uint4*)(aHi + px * 88 + k * 8) = *(const uint4*)hi8;
            *(uint4*)(aLo + px * 88 + k * 8) = *(const uint4*)lo8;
        }

        CP_WAIT1();                      // B(g) arrived (<=1 group pending)
        __syncthreads();

        // ---- wmma contraction for group g ----
        const __nv_bfloat16* bh = smB + (g & 1) * (2 * DBG_);
        const __nv_bfloat16* blo = bh + DBG_;
        const int arow = (w * 16) * 88;
#pragma unroll
        for (int kt = 0; kt < 5; ++kt) {
            wmma::fragment<wmma::matrix_a, 16, 16, 16, __nv_bfloat16,
                           wmma::row_major> fa_h, fa_l;
            wmma::load_matrix_sync(fa_h, aHi + arow + kt * 16, 88);
            wmma::load_matrix_sync(fa_l, aLo + arow + kt * 16, 88);
#pragma unroll
            for (int nt = 0; nt < 4; ++nt) {
                wmma::fragment<wmma::matrix_b, 16, 16, 16, __nv_bfloat16,
                               wmma::row_major> fb;
                wmma::load_matrix_sync(fb, bh + kt * 16 * 72 + nt * 16, 72);
                wmma::mma_sync(acc[nt], fa_h, fb, acc[nt]);
                wmma::mma_sync(acc[nt], fa_l, fb, acc[nt]);
                wmma::load_matrix_sync(fb, blo + kt * 16 * 72 + nt * 16, 72);
                wmma::mma_sync(acc[nt], fa_h, fb, acc[nt]);
            }
        }
    }

    // ---- epilogue ----
    __syncthreads();
    float* smf = (float*)(sm + A_OFF);   // 128 x 68 fp32 (reuses A region)
#pragma unroll
    for (int nt = 0; nt < 4; ++nt)
        wmma::store_matrix_sync(smf + (w * 16) * 68 + nt * 16, acc[nt], 68,
                                wmma::mem_row_major);
    __syncthreads();

    if (out) {
#pragma unroll 1
        for (int i = tid; i < 64 * 128; i += 256) {
            const int c = i >> 7;
            const int p = i & 127;
            float v = smf[p * 68 + c] + bias[c];
            if (act) v = (v > 0.f) ? v : SLOPE_ * v;
            const int py = by + (p >> 4);
            const int px = bx + (p & 15);
            out[((size_t)b * 64 + c) * HW_ + py * W_ + px] = v;
        }
    }
    if (outT) {
#pragma unroll 1
        for (int i = tid; i < 128 * 16; i += 256) {
            const int c4 = i & 15;
            const int p  = i >> 4;
            float4 v = *(float4*)(smf + p * 68 + 4 * c4);
            v.x += bias[4 * c4];
            v.y += bias[4 * c4 + 1];
            v.z += bias[4 * c4 + 2];
            v.w += bias[4 * c4 + 3];
            if (act) {
                v.x = (v.x > 0.f) ? v.x : SLOPE_ * v.x;
                v.y = (v.y > 0.f) ? v.y : SLOPE_ * v.y;
                v.z = (v.z > 0.f) ? v.z : SLOPE_ * v.z;
                v.w = (v.w > 0.f) ? v.w : SLOPE_ * v.w;
            }
            const int py = by + (p >> 4);
            const int px = bx + (p & 15);
            *(float4*)(outT + ((size_t)b * HW_ + py * W_ + px) * 64 + 4 * c4) = v;
        }
    }
}

// ---------------------------------------------------------------------------
// Launch
// ---------------------------------------------------------------------------
extern "C" void kernel_launch(void* const* d_in, const int* in_sizes, int n_in,
                              void* d_out, int out_size)
{
    const float* nbr     = (const float*)d_in[0];
    const float* ref     = (const float*)d_in[1];
    const float* w_off1  = (const float*)d_in[2];
    const float* b_off1  = (const float*)d_in[3];
    const float* w_off2  = (const float*)d_in[4];
    const float* b_off2  = (const float*)d_in[5];
    const float* w_co    = (const float*)d_in[6];
    const float* b_co    = (const float*)d_in[7];
    const float* w_dcn   = (const float*)d_in[8];
    const float* b_dcn   = (const float*)d_in[9];
    const float* w_coff1 = (const float*)d_in[10];
    const float* b_coff1 = (const float*)d_in[11];
    const float* w_coff2 = (const float*)d_in[12];
    const float* b_coff2 = (const float*)d_in[13];
    const float* w_cco   = (const float*)d_in[14];
    const float* b_cco   = (const float*)d_in[15];
    const float* w_cdcn  = (const float*)d_in[16];
    const float* b_cdcn  = (const float*)d_in[17];
    float* outp = (float*)d_out;

    void *pA, *pB, *pCO, *pNT, *pRT, *pFT;
    void *pw1, *pw2, *pw3, *pw4, *pw5, *pw6, *pd1, *pd2;
    cudaGetSymbolAddress(&pA,  g_bufA);
    cudaGetSymbolAddress(&pB,  g_bufB);
    cudaGetSymbolAddress(&pCO, g_co);
    cudaGetSymbolAddress(&pNT, g_nbrT);
    cudaGetSymbolAddress(&pRT, g_refT);
    cudaGetSymbolAddress(&pFT, g_featT);
    cudaGetSymbolAddress(&pw1, g_wb1);
    cudaGetSymbolAddress(&pw2, g_wb2);
    cudaGetSymbolAddress(&pw3, g_wb3);
    cudaGetSymbolAddress(&pw4, g_wb4);
    cudaGetSymbolAddress(&pw5, g_wb5);
    cudaGetSymbolAddress(&pw6, g_wb6);
    cudaGetSymbolAddress(&pd1, g_wd1);
    cudaGetSymbolAddress(&pd2, g_wd2);
    float* bufA  = (float*)pA;
    float* bufB  = (float*)pB;
    float* bufCO = (float*)pCO;
    float* nbrT  = (float*)pNT;
    float* refT  = (float*)pRT;
    float* featT = (float*)pFT;

    // conv smem (R11 values)
    constexpr int SM64 = 2 * 2 * 64 * 72 * 2 + 2 * 180 * 72 * 2;   // 88704
    constexpr int SM80 = 2 * 2 * 64 * 88 * 2 + 2 * 180 * 72 * 2;   // 96896
    constexpr int SMD  = 2 * (2 * DBG_ * 2) + 2 * 128 * 88 * 2;    // 46080+45056=91136
    cudaFuncSetAttribute(tconv_k<64, 64, 2>, cudaFuncAttributeMaxDynamicSharedMemorySize, SM64);
    cudaFuncSetAttribute(tconv_k<64, 64, 1>, cudaFuncAttributeMaxDynamicSharedMemorySize, SM64);
    cudaFuncSetAttribute(tconv_k<72, 80, 1>, cudaFuncAttributeMaxDynamicSharedMemorySize, SM80);
    cudaFuncSetAttribute(dcnw_k, cudaFuncAttributeMaxDynamicSharedMemorySize, SMD);

    const dim3 blk(256);
    const dim3 gT(HW_ / 64, B_);
    const dim3 gC(W_ / 16, H_ / 8, B_);          // (10, 20, 4)
    const dim3 gC3(W_ / 16, H_ / 8, B_ * 3);     // (10, 20, 12)
    const dim3 gD(W_ / 16, H_ / 8, B_);          // dcn: 128-px tiles

    // transposes
    t_k<<<gT, blk>>>(nbr, nbrT);
    t_k<<<gT, blk>>>(ref, refT);

    // weight packing
    pack_k<<<dim3(72, 1), blk>>>(w_off1, 128, 64, 64, 72, 2, (__nv_bfloat16*)pw1);
    pack_k<<<dim3(36, 1), blk>>>(w_off2,  64, 64, 64, 72, 1, (__nv_bfloat16*)pw2);
    pack_k<<<dim3(18, 3), blk>>>(w_co,    64, 72, 80, 88, 1, (__nv_bfloat16*)pw3);
    pack_k<<<dim3(72, 1), blk>>>(w_coff1, 128, 64, 64, 72, 2, (__nv_bfloat16*)pw4);
    pack_k<<<dim3(36, 1), blk>>>(w_coff2,  64, 64, 64, 72, 1, (__nv_bfloat16*)pw5);
    pack_k<<<dim3(18, 3), blk>>>(w_cco,    64, 72, 80, 88, 1, (__nv_bfloat16*)pw6);
    pack_dcn<<<dim3(180), blk>>>(w_dcn,  (__nv_bfloat16*)pd1);
    pack_dcn<<<dim3(180), blk>>>(w_cdcn, (__nv_bfloat16*)pd2);

    // ---- first alignment stage ----
    tconv_k<64, 64, 2><<<gC, blk, SM64>>>(nbrT, refT, (__nv_bfloat16*)pw1, b_off1, bufA, 1);
    tconv_k<64, 64, 1><<<gC, blk, SM64>>>(bufA, nullptr, (__nv_bfloat16*)pw2, b_off2, bufB, 1);
    tconv_k<72, 80, 1><<<gC3, blk, SM80>>>(bufB, nullptr, (__nv_bfloat16*)pw3, b_co, bufCO, 0);
    dcnw_k<<<gD, blk, SMD>>>(nbrT, bufCO, (__nv_bfloat16*)pd1, b_dcn, nullptr, featT, 1);

    // ---- cascade stage ----
    tconv_k<64, 64, 2><<<gC, blk, SM64>>>(featT, refT, (__nv_bfloat16*)pw4, b_coff1, bufA, 1);
    tconv_k<64, 64, 1><<<gC, blk, SM64>>>(bufA, nullptr, (__nv_bfloat16*)pw5, b_coff2, bufB, 1);
    tconv_k<72, 80, 1><<<gC3, blk, SM80>>>(bufB, nullptr, (__nv_bfloat16*)pw6, b_cco, bufCO, 0);
    dcnw_k<<<gD, blk, SMD>>>(featT, bufCO, (__nv_bfloat16*)pd2, b_cdcn, outp, nullptr, 1);
}

// round 16
// speedup vs baseline: 1.6365x; 1.3280x over previous
#include <cuda_runtime.h>
#include <cuda_bf16.h>
#include <cstdint>

// Problem constants (fixed shapes)
#define B_  4
#define H_  160
#define W_  160
#define HW_ (H_ * W_)
#define OC_ 216   // 3 * DG * KK
#define DG_ 8
#define KK_ 9
#define SLOPE_ 0.1f

// ---------------------------------------------------------------------------
// Helpers
// ---------------------------------------------------------------------------
__device__ __forceinline__ void cp16(uint32_t s, const void* g) {
    asm volatile("cp.async.cg.shared.global [%0], [%1], 16;" :: "r"(s), "l"(g));
}
#define CP_COMMIT() asm volatile("cp.async.commit_group;")
#define CP_WAIT0()  asm volatile("cp.async.wait_group 0;" ::: "memory")
#define CP_WAIT1()  asm volatile("cp.async.wait_group 1;" ::: "memory")

// ldmatrix / mma.sync (sm_80-level PTX; safe for plain sm_103 target)
__device__ __forceinline__ void ldsm4(uint32_t addr, uint32_t& r0, uint32_t& r1,
                                      uint32_t& r2, uint32_t& r3) {
    asm volatile("ldmatrix.sync.aligned.m8n8.x4.shared.b16 {%0,%1,%2,%3}, [%4];"
                 : "=r"(r0), "=r"(r1), "=r"(r2), "=r"(r3) : "r"(addr));
}
__device__ __forceinline__ void ldsm2t(uint32_t addr, uint32_t& r0, uint32_t& r1) {
    asm volatile("ldmatrix.sync.aligned.m8n8.x2.trans.shared.b16 {%0,%1}, [%2];"
                 : "=r"(r0), "=r"(r1) : "r"(addr));
}
__device__ __forceinline__ void mma16816(float* d, uint32_t a0, uint32_t a1,
                                         uint32_t a2, uint32_t a3,
                                         uint32_t b0, uint32_t b1) {
    asm volatile("mma.sync.aligned.m16n8k16.row.col.f32.bf16.bf16.f32 "
                 "{%0,%1,%2,%3}, {%4,%5,%6,%7}, {%8,%9}, {%0,%1,%2,%3};"
                 : "+f"(d[0]), "+f"(d[1]), "+f"(d[2]), "+f"(d[3])
                 : "r"(a0), "r"(a1), "r"(a2), "r"(a3), "r"(b0), "r"(b1));
}

// ---------------------------------------------------------------------------
// Scratch buffers (static device globals; no runtime allocation allowed)
// ---------------------------------------------------------------------------
__device__ float g_bufA [B_ * HW_ * 64];   // NHWC activations
__device__ float g_bufB [B_ * HW_ * 64];   // NHWC activations
__device__ float g_co   [B_ * OC_ * HW_];  // NCHW offsets/masks
__device__ float g_nbrT [B_ * HW_ * 64];   // NHWC
__device__ float g_refT [B_ * HW_ * 64];   // NHWC
__device__ float g_featT[B_ * HW_ * 64];   // NHWC

// packed bf16 hi/lo weight blobs: [slice][half][tap][{hi,lo}][k=64][NPs]
__device__ __nv_bfloat16 g_wb1[2 * 9 * 2 * 64 * 72];       // conv1 (2 halves)
__device__ __nv_bfloat16 g_wb2[9 * 2 * 64 * 72];           // conv2
__device__ __nv_bfloat16 g_wb3[3 * 9 * 2 * 64 * 88];       // co (3 slices, NP=80)
__device__ __nv_bfloat16 g_wb4[2 * 9 * 2 * 64 * 72];
__device__ __nv_bfloat16 g_wb5[9 * 2 * 64 * 72];
__device__ __nv_bfloat16 g_wb6[3 * 9 * 2 * 64 * 88];

// packed dcn weight blobs: [g][{hi,lo}][k'=80][n=72]  (k' = tap*8 + c)
#define DBG_ (80 * 72)
__device__ __nv_bfloat16 g_wd1[DG_ * 2 * DBG_];
__device__ __nv_bfloat16 g_wd2[DG_ * 2 * DBG_];

// ---------------------------------------------------------------------------
// NCHW -> NHWC transpose
// ---------------------------------------------------------------------------
__global__ __launch_bounds__(256)
void t_k(const float* __restrict__ in, float* __restrict__ out)
{
    __shared__ float s[64][65];
    const int tid = threadIdx.x;
    const int b = blockIdx.y;
    const int p0 = blockIdx.x * 64;
#pragma unroll 1
    for (int i = tid; i < 64 * 64; i += 256) {
        const int c = i >> 6, p = i & 63;
        s[c][p] = in[((size_t)b * 64 + c) * HW_ + p0 + p];
    }
    __syncthreads();
#pragma unroll 1
    for (int i = tid; i < 64 * 64; i += 256) {
        const int p = i >> 6, c = i & 63;
        out[((size_t)b * HW_ + p0 + p) * 64 + c] = s[c][p];
    }
}

// ---------------------------------------------------------------------------
// Conv weight packing (unchanged)
// ---------------------------------------------------------------------------
__global__ __launch_bounds__(256)
void pack_k(const float* __restrict__ w, int cin_total, int nout, int np,
            int nps, int halves, __nv_bfloat16* __restrict__ blob)
{
    const int slice = blockIdx.y;
    const int cout0 = slice * nout;
    const int taphalf = 64 * nps;
    const int tapsz = 2 * taphalf;
    const int slice_stride = halves * 9 * tapsz;
    const int total = halves * 9 * 64 * np;
#pragma unroll 1
    for (int i = blockIdx.x * 256 + threadIdx.x; i < total; i += gridDim.x * 256) {
        const int n = i % np;
        const int k = (i / np) & 63;
        const int t = (i / (np * 64)) % 9;
        const int h = i / (np * 64 * 9);
        float x = 0.f;
        if (n < nout)
            x = w[((size_t)(cout0 + n) * cin_total + h * 64 + k) * 9 + t];
        const __nv_bfloat16 hi = __float2bfloat16(x);
        const __nv_bfloat16 lo = __float2bfloat16(x - __bfloat162float(hi));
        __nv_bfloat16* dst = blob + (size_t)slice * slice_stride
                             + (h * 9 + t) * tapsz + k * nps + n;
        dst[0] = hi;
        dst[taphalf] = lo;
    }
}

// ---------------------------------------------------------------------------
// DCN weight packing (unchanged)
// ---------------------------------------------------------------------------
__global__ __launch_bounds__(256)
void pack_dcn(const float* __restrict__ w, __nv_bfloat16* __restrict__ blob)
{
    const int total = DG_ * 80 * 72;
#pragma unroll 1
    for (int i = blockIdx.x * 256 + threadIdx.x; i < total; i += gridDim.x * 256) {
        const int n = i % 72;
        const int k = (i / 72) % 80;
        const int g = i / (72 * 80);
        float x = 0.f;
        if (n < 64 && k < 72)
            x = w[((size_t)n * 64 + g * 8 + (k & 7)) * 9 + (k >> 3)];
        const __nv_bfloat16 hi = __float2bfloat16(x);
        const __nv_bfloat16 lo = __float2bfloat16(x - __bfloat162float(hi));
        blob[(size_t)g * 2 * DBG_ + k * 72 + n]        = hi;
        blob[(size_t)g * 2 * DBG_ + DBG_ + k * 72 + n] = lo;
    }
}

// ---------------------------------------------------------------------------
// conv3x3: implicit GEMM via ldmatrix + mma.sync.m16n8k16 (3-pass hi/lo).
// Same staging / sync structure as the R11/R15 winner; only the fragment
// loads and MMA issue changed (guaranteed LDSM).
// ---------------------------------------------------------------------------
template <int NOUT, int NP, int HALVES>
__global__ __launch_bounds__(256, 2)
void tconv_k(const float* __restrict__ in0, const float* __restrict__ in1,
             const __nv_bfloat16* __restrict__ blob,
             const float* __restrict__ bias, float* __restrict__ out, int act)
{
    constexpr int NPs     = NP + 8;
    constexpr int NT8     = NOUT / 8;           // 8 (N=64) or 9 (N=72)
    constexpr int TAPHALF = 64 * NPs;
    constexpr int TAPSZ   = 2 * TAPHALF;
    constexpr int B_BYTES = TAPSZ * 2;
    constexpr int A_OFF   = B_BYTES;
    constexpr int A_BYTES = 180 * 72 * 2;
    constexpr int NSLICE  = (NOUT == 72) ? 3 : 1;
    constexpr int LDO     = NP + 4;

    extern __shared__ uint8_t sm[];
    __nv_bfloat16* aHiB = (__nv_bfloat16*)(sm + A_OFF);
    __nv_bfloat16* aLoB = (__nv_bfloat16*)(sm + A_OFF + A_BYTES);
    uint32_t* aHi32 = (uint32_t*)aHiB;
    uint32_t* aLo32 = (uint32_t*)aLoB;
    const uint32_t smb = (uint32_t)__cvta_generic_to_shared(sm);
    const uint32_t smbAhi = smb + A_OFF;
    const uint32_t smbAlo = smbAhi + A_BYTES;

    const int tid  = threadIdx.x;
    const int w    = tid >> 5;
    const int lane = tid & 31;
    const int slice = blockIdx.z % NSLICE;
    const int b     = blockIdx.z / NSLICE;
    const int by = blockIdx.y * 8;
    const int bx = blockIdx.x * 16;

    float acc[NT8][4];
#pragma unroll
    for (int nt = 0; nt < NT8; ++nt)
#pragma unroll
        for (int q = 0; q < 4; ++q) acc[nt][q] = 0.f;

    const __nv_bfloat16* bl = blob + (size_t)slice * (HALVES * 9 * TAPSZ);

#pragma unroll 1
    for (int h = 0; h < HALVES; ++h) {
        __syncthreads();

        const float* src = ((HALVES == 2 && h == 1) ? in1 : in0) + (size_t)b * HW_ * 64;
#pragma unroll 1
        for (int i = tid; i < 180 * 32; i += 256) {
            const int pix = i >> 5;
            const int j   = i & 31;
            const int pr  = pix / 18, pc = pix - pr * 18;
            const int gy = by + pr - 1, gx = bx + pc - 1;
            float2 v = make_float2(0.f, 0.f);
            if (gy >= 0 && gy < H_ && gx >= 0 && gx < W_)
                v = *(const float2*)(src + ((size_t)(gy * W_ + gx)) * 64 + 2 * j);
            const __nv_bfloat16 h0 = __float2bfloat16(v.x);
            const __nv_bfloat16 h1 = __float2bfloat16(v.y);
            const __nv_bfloat16 l0 = __float2bfloat16(v.x - __bfloat162float(h0));
            const __nv_bfloat16 l1 = __float2bfloat16(v.y - __bfloat162float(h1));
            aHi32[pix * 36 + j] = (uint32_t)__bfloat16_as_ushort(h0) |
                                  ((uint32_t)__bfloat16_as_ushort(h1) << 16);
            aLo32[pix * 36 + j] = (uint32_t)__bfloat16_as_ushort(l0) |
                                  ((uint32_t)__bfloat16_as_ushort(l1) << 16);
        }

#pragma unroll 1
        for (int t = 0; t < 9; ++t) {
            __syncthreads();
            const __nv_bfloat16* bsrc = bl + (size_t)(h * 9 + t) * TAPSZ;
#pragma unroll 1
            for (int i = tid * 16; i < B_BYTES; i += 256 * 16)
                cp16(smb + i, (const uint8_t*)bsrc + i);
            CP_COMMIT();
            CP_WAIT0();
            __syncthreads();

            const int ky = t / 3, kx = t - ky * 3;
            const int abase = ((w + ky) * 18 + kx) * 72;
            // lane-mapped A address (row = lane%16, k-half = lane/16)
            const uint32_t aoff = (uint32_t)((abase + (lane & 15) * 72) * 2)
                                  + (uint32_t)((lane >> 4) * 16);

#pragma unroll
            for (int kc = 0; kc < 4; ++kc) {
                uint32_t ah0, ah1, ah2, ah3, al0, al1, al2, al3;
                ldsm4(smbAhi + aoff + kc * 32, ah0, ah1, ah2, ah3);
                ldsm4(smbAlo + aoff + kc * 32, al0, al1, al2, al3);
                const uint32_t brow = smb +
                    (uint32_t)(((kc * 16 + (lane & 15)) * NPs) * 2);
#pragma unroll
                for (int nt = 0; nt < NT8; ++nt) {
                    uint32_t bh0, bh1, bl0, bl1;
                    ldsm2t(brow + nt * 16, bh0, bh1);
                    mma16816(acc[nt], ah0, ah1, ah2, ah3, bh0, bh1);
                    mma16816(acc[nt], al0, al1, al2, al3, bh0, bh1);
                    ldsm2t(brow + TAPHALF * 2 + nt * 16, bl0, bl1);
                    mma16816(acc[nt], ah0, ah1, ah2, ah3, bl0, bl1);
                }
            }
        }
    }

    // ---- epilogue: acc regs -> smem -> bias/act -> gmem ----
    __syncthreads();
    float* smf = (float*)(sm + A_OFF);
    {
        const int r0 = lane >> 2;
        const int c0 = (lane & 3) * 2;
#pragma unroll
        for (int nt = 0; nt < NT8; ++nt) {
            float* d = smf + (w * 16 + r0) * LDO + nt * 8 + c0;
            d[0] = acc[nt][0];
            d[1] = acc[nt][1];
            d += 8 * LDO;
            d[0] = acc[nt][2];
            d[1] = acc[nt][3];
        }
    }
    __syncthreads();

    if (NOUT == 64) {
#pragma unroll 1
        for (int i = tid; i < 128 * 16; i += 256) {
            const int c4 = i & 15;
            const int p  = i >> 4;
            float4 v = *(float4*)(smf + p * LDO + 4 * c4);
            v.x += bias[4 * c4];
            v.y += bias[4 * c4 + 1];
            v.z += bias[4 * c4 + 2];
            v.w += bias[4 * c4 + 3];
            if (act) {
                v.x = (v.x > 0.f) ? v.x : SLOPE_ * v.x;
                v.y = (v.y > 0.f) ? v.y : SLOPE_ * v.y;
                v.z = (v.z > 0.f) ? v.z : SLOPE_ * v.z;
                v.w = (v.w > 0.f) ? v.w : SLOPE_ * v.w;
            }
            const int py = by + (p >> 4);
            const int px = bx + (p & 15);
            *(float4*)(out + ((size_t)b * HW_ + py * W_ + px) * 64 + 4 * c4) = v;
        }
    } else {
        const float* bs = bias + slice * NOUT;
#pragma unroll 1
        for (int i = tid; i < NOUT * 128; i += 256) {
            const int c = i >> 7;
            const int p = i & 127;
            float v = smf[p * LDO + c] + bs[c];
            if (act) v = (v > 0.f) ? v : SLOPE_ * v;
            const int py = by + (p >> 4);
            const int px = bx + (p & 15);
            out[((size_t)b * OC_ + slice * NOUT + c) * HW_ + py * W_ + px] = v;
        }
    }
}

// ---------------------------------------------------------------------------
// DCN with ldmatrix + mma.sync contraction (gather path unchanged from R15).
// N restricted to 8 n8-tiles (cols 0..63; pad cols were all-zero anyway).
// ---------------------------------------------------------------------------
__global__ __launch_bounds__(256, 2)
void dcnw_k(const float* __restrict__ xT, const float* __restrict__ co,
            const __nv_bfloat16* __restrict__ wblob,
            const float* __restrict__ bias,
            float* __restrict__ out, float* __restrict__ outT, int act)
{
    constexpr int CH_B  = 2 * DBG_ * 2;       // bytes per group chunk (hi+lo)
    constexpr int A_OFF = 2 * CH_B;           // ring of 2
    constexpr int A_ELE = 128 * 88;

    extern __shared__ uint8_t sm[];
    __nv_bfloat16* aHi = (__nv_bfloat16*)(sm + A_OFF);
    __nv_bfloat16* aLo = aHi + A_ELE;
    const uint32_t smb = (uint32_t)__cvta_generic_to_shared(sm);
    const uint32_t smbAhi = smb + A_OFF;
    const uint32_t smbAlo = smbAhi + A_ELE * 2;

    const int tid = threadIdx.x;
    const int w   = tid >> 5;
    const int lane = tid & 31;
    const int b   = blockIdx.z;
    const int by  = blockIdx.y * 8;
    const int bx  = blockIdx.x * 16;

    const float* cob = co + (size_t)b * OC_ * HW_;
    const float* xb  = xT + (size_t)b * HW_ * 64;

    // zero K-pad columns (72..79) once
    {
        const int row = tid & 127;
        __nv_bfloat16* dst = ((tid < 128) ? aHi : aLo) + row * 88 + 72;
        *(uint4*)dst = make_uint4(0, 0, 0, 0);
    }

    float acc[8][4];
#pragma unroll
    for (int nt = 0; nt < 8; ++nt)
#pragma unroll
        for (int q = 0; q < 4; ++q) acc[nt][q] = 0.f;

    auto prefetchB = [&](int g) {
        const uint8_t* src = (const uint8_t*)(wblob + (size_t)g * 2 * DBG_);
        const uint32_t dst = smb + (uint32_t)((g & 1) * CH_B);
#pragma unroll 1
        for (int i = tid * 16; i < CH_B; i += 256 * 16)
            cp16(dst + i, src + i);
    };
    prefetchB(0); CP_COMMIT();

#pragma unroll 1
    for (int g = 0; g < DG_; ++g) {
        __syncthreads();
        if (g + 1 < DG_) prefetchB(g + 1);
        CP_COMMIT();

        // ---- gather A panel for group g ----
#pragma unroll 1
        for (int i = tid; i < 128 * 9; i += 256) {
            const int px = i & 127;
            const int k  = i >> 7;
            const int y = by + (px >> 4);
            const int x = bx + (px & 15);
            const int pix = y * W_ + x;

            const float offy = cob[(size_t)(g * 18 + 2 * k    ) * HW_ + pix];
            const float offx = cob[(size_t)(g * 18 + 2 * k + 1) * HW_ + pix];
            const float ml   = cob[(size_t)(144 + g * 9 + k   ) * HW_ + pix];
            const float m    = 1.f / (1.f + __expf(-ml));

            const float py = (float)y + (float)(k / 3 - 1) + offy;
            const float pxf = (float)x + (float)(k % 3 - 1) + offx;
            const float y0f = floorf(py), x0f = floorf(pxf);
            const float ly = py - y0f,  lx = pxf - x0f;
            const int y0 = (int)y0f,    x0 = (int)x0f;

            const float w00 = (1.f - ly) * (1.f - lx) * m;
            const float w01 = (1.f - ly) * lx * m;
            const float w10 = ly * (1.f - lx) * m;
            const float w11 = ly * lx * m;

            const bool iy0 = (y0 >= 0)     && (y0 < H_);
            const bool iy1 = (y0 + 1 >= 0) && (y0 + 1 < H_);
            const bool ix0 = (x0 >= 0)     && (x0 < W_);
            const bool ix1 = (x0 + 1 >= 0) && (x0 + 1 < W_);

            float4 c00a = {0,0,0,0}, c00b = {0,0,0,0};
            float4 c01a = {0,0,0,0}, c01b = {0,0,0,0};
            float4 c10a = {0,0,0,0}, c10b = {0,0,0,0};
            float4 c11a = {0,0,0,0}, c11b = {0,0,0,0};
            if (iy0 && ix0) {
                const float4* p = (const float4*)(xb + ((size_t)(y0 * W_ + x0)) * 64 + g * 8);
                c00a = __ldg(p); c00b = __ldg(p + 1);
            }
            if (iy0 && ix1) {
                const float4* p = (const float4*)(xb + ((size_t)(y0 * W_ + x0 + 1)) * 64 + g * 8);
                c01a = __ldg(p); c01b = __ldg(p + 1);
            }
            if (iy1 && ix0) {
                const float4* p = (const float4*)(xb + ((size_t)((y0 + 1) * W_ + x0)) * 64 + g * 8);
                c10a = __ldg(p); c10b = __ldg(p + 1);
            }
            if (iy1 && ix1) {
                const float4* p = (const float4*)(xb + ((size_t)((y0 + 1) * W_ + x0 + 1)) * 64 + g * 8);
                c11a = __ldg(p); c11b = __ldg(p + 1);
            }

            float s[8];
            s[0] = w00*c00a.x + w01*c01a.x + w10*c10a.x + w11*c11a.x;
            s[1] = w00*c00a.y + w01*c01a.y + w10*c10a.y + w11*c11a.y;
            s[2] = w00*c00a.z + w01*c01a.z + w10*c10a.z + w11*c11a.z;
            s[3] = w00*c00a.w + w01*c01a.w + w10*c10a.w + w11*c11a.w;
            s[4] = w00*c00b.x + w01*c01b.x + w10*c10b.x + w11*c11b.x;
            s[5] = w00*c00b.y + w01*c01b.y + w10*c10b.y + w11*c11b.y;
            s[6] = w00*c00b.z + w01*c01b.z + w10*c10b.z + w11*c11b.z;
            s[7] = w00*c00b.w + w01*c01b.w + w10*c10b.w + w11*c11b.w;

            __nv_bfloat16 hi8[8], lo8[8];
#pragma unroll
            for (int c = 0; c < 8; ++c) {
                hi8[c] = __float2bfloat16(s[c]);
                lo8[c] = __float2bfloat16(s[c] - __bfloat162float(hi8[c]));
            }
            *(uint4*)(aHi + px * 88 + k * 8) = *(const uint4*)hi8;
            *(uint4*)(aLo + px * 88 + k * 8) = *(const uint4*)lo8;
        }

        CP_WAIT1();
        __syncthreads();

        // ---- mma contraction for group g ----
        const uint32_t bBase = smb + (uint32_t)((g & 1) * CH_B);
        const uint32_t aoff = (uint32_t)(((w * 16 + (lane & 15)) * 88) * 2)
                              + (uint32_t)((lane >> 4) * 16);
#pragma unroll
        for (int kt = 0; kt < 5; ++kt) {
            uint32_t ah0, ah1, ah2, ah3, al0, al1, al2, al3;
            ldsm4(smbAhi + aoff + kt * 32, ah0, ah1, ah2, ah3);
            ldsm4(smbAlo + aoff + kt * 32, al0, al1, al2, al3);
            const uint32_t brow = bBase +
                (uint32_t)(((kt * 16 + (lane & 15)) * 72) * 2);
#pragma unroll
            for (int nt = 0; nt < 8; ++nt) {
                uint32_t bh0, bh1, bl0, bl1;
                ldsm2t(brow + nt * 16, bh0, bh1);
                mma16816(acc[nt], ah0, ah1, ah2, ah3, bh0, bh1);
                mma16816(acc[nt], al0, al1, al2, al3, bh0, bh1);
                ldsm2t(brow + DBG_ * 2 + nt * 16, bl0, bl1);
                mma16816(acc[nt], ah0, ah1, ah2, ah3, bl0, bl1);
            }
        }
    }

    // ---- epilogue ----
    __syncthreads();
    float* smf = (float*)(sm + A_OFF);   // 128 x 68 fp32
    {
        const int r0 = lane >> 2;
        const int c0 = (lane & 3) * 2;
#pragma unroll
        for (int nt = 0; nt < 8; ++nt) {
            float* d = smf + (w * 16 + r0) * 68 + nt * 8 + c0;
            d[0] = acc[nt][0];
            d[1] = acc[nt][1];
            d += 8 * 68;
            d[0] = acc[nt][2];
            d[1] = acc[nt][3];
        }
    }
    __syncthreads();

    if (out) {
#pragma unroll 1
        for (int i = tid; i < 64 * 128; i += 256) {
            const int c = i >> 7;
            const int p = i & 127;
            float v = smf[p * 68 + c] + bias[c];
            if (act) v = (v > 0.f) ? v : SLOPE_ * v;
            const int py = by + (p >> 4);
            const int px = bx + (p & 15);
            out[((size_t)b * 64 + c) * HW_ + py * W_ + px] = v;
        }
    }
    if (outT) {
#pragma unroll 1
        for (int i = tid; i < 128 * 16; i += 256) {
            const int c4 = i & 15;
            const int p  = i >> 4;
            float4 v = *(float4*)(smf + p * 68 + 4 * c4);
            v.x += bias[4 * c4];
            v.y += bias[4 * c4 + 1];
            v.z += bias[4 * c4 + 2];
            v.w += bias[4 * c4 + 3];
            if (act) {
                v.x = (v.x > 0.f) ? v.x : SLOPE_ * v.x;
                v.y = (v.y > 0.f) ? v.y : SLOPE_ * v.y;
                v.z = (v.z > 0.f) ? v.z : SLOPE_ * v.z;
                v.w = (v.w > 0.f) ? v.w : SLOPE_ * v.w;
            }
            const int py = by + (p >> 4);
            const int px = bx + (p & 15);
            *(float4*)(outT + ((size_t)b * HW_ + py * W_ + px) * 64 + 4 * c4) = v;
        }
    }
}

// ---------------------------------------------------------------------------
// Launch
// ---------------------------------------------------------------------------
extern "C" void kernel_launch(void* const* d_in, const int* in_sizes, int n_in,
                              void* d_out, int out_size)
{
    const float* nbr     = (const float*)d_in[0];
    const float* ref     = (const float*)d_in[1];
    const float* w_off1  = (const float*)d_in[2];
    const float* b_off1  = (const float*)d_in[3];
    const float* w_off2  = (const float*)d_in[4];
    const float* b_off2  = (const float*)d_in[5];
    const float* w_co    = (const float*)d_in[6];
    const float* b_co    = (const float*)d_in[7];
    const float* w_dcn   = (const float*)d_in[8];
    const float* b_dcn   = (const float*)d_in[9];
    const float* w_coff1 = (const float*)d_in[10];
    const float* b_coff1 = (const float*)d_in[11];
    const float* w_coff2 = (const float*)d_in[12];
    const float* b_coff2 = (const float*)d_in[13];
    const float* w_cco   = (const float*)d_in[14];
    const float* b_cco   = (const float*)d_in[15];
    const float* w_cdcn  = (const float*)d_in[16];
    const float* b_cdcn  = (const float*)d_in[17];
    float* outp = (float*)d_out;

    void *pA, *pB, *pCO, *pNT, *pRT, *pFT;
    void *pw1, *pw2, *pw3, *pw4, *pw5, *pw6, *pd1, *pd2;
    cudaGetSymbolAddress(&pA,  g_bufA);
    cudaGetSymbolAddress(&pB,  g_bufB);
    cudaGetSymbolAddress(&pCO, g_co);
    cudaGetSymbolAddress(&pNT, g_nbrT);
    cudaGetSymbolAddress(&pRT, g_refT);
    cudaGetSymbolAddress(&pFT, g_featT);
    cudaGetSymbolAddress(&pw1, g_wb1);
    cudaGetSymbolAddress(&pw2, g_wb2);
    cudaGetSymbolAddress(&pw3, g_wb3);
    cudaGetSymbolAddress(&pw4, g_wb4);
    cudaGetSymbolAddress(&pw5, g_wb5);
    cudaGetSymbolAddress(&pw6, g_wb6);
    cudaGetSymbolAddress(&pd1, g_wd1);
    cudaGetSymbolAddress(&pd2, g_wd2);
    float* bufA  = (float*)pA;
    float* bufB  = (float*)pB;
    float* bufCO = (float*)pCO;
    float* nbrT  = (float*)pNT;
    float* refT  = (float*)pRT;
    float* featT = (float*)pFT;

    constexpr int SM64 = 2 * 2 * 64 * 72 * 2 + 2 * 180 * 72 * 2;   // 88704
    constexpr int SM80 = 2 * 2 * 64 * 88 * 2 + 2 * 180 * 72 * 2;   // 96896
    constexpr int SMD  = 2 * (2 * DBG_ * 2) + 2 * 128 * 88 * 2;    // 91136
    cudaFuncSetAttribute(tconv_k<64, 64, 2>, cudaFuncAttributeMaxDynamicSharedMemorySize, SM64);
    cudaFuncSetAttribute(tconv_k<64, 64, 1>, cudaFuncAttributeMaxDynamicSharedMemorySize, SM64);
    cudaFuncSetAttribute(tconv_k<72, 80, 1>, cudaFuncAttributeMaxDynamicSharedMemorySize, SM80);
    cudaFuncSetAttribute(dcnw_k, cudaFuncAttributeMaxDynamicSharedMemorySize, SMD);

    const dim3 blk(256);
    const dim3 gT(HW_ / 64, B_);
    const dim3 gC(W_ / 16, H_ / 8, B_);          // (10, 20, 4)
    const dim3 gC3(W_ / 16, H_ / 8, B_ * 3);     // (10, 20, 12)
    const dim3 gD(W_ / 16, H_ / 8, B_);          // dcn: 128-px tiles

    // transposes
    t_k<<<gT, blk>>>(nbr, nbrT);
    t_k<<<gT, blk>>>(ref, refT);

    // weight packing
    pack_k<<<dim3(72, 1), blk>>>(w_off1, 128, 64, 64, 72, 2, (__nv_bfloat16*)pw1);
    pack_k<<<dim3(36, 1), blk>>>(w_off2,  64, 64, 64, 72, 1, (__nv_bfloat16*)pw2);
    pack_k<<<dim3(18, 3), blk>>>(w_co,    64, 72, 80, 88, 1, (__nv_bfloat16*)pw3);
    pack_k<<<dim3(72, 1), blk>>>(w_coff1, 128, 64, 64, 72, 2, (__nv_bfloat16*)pw4);
    pack_k<<<dim3(36, 1), blk>>>(w_coff2,  64, 64, 64, 72, 1, (__nv_bfloat16*)pw5);
    pack_k<<<dim3(18, 3), blk>>>(w_cco,    64, 72, 80, 88, 1, (__nv_bfloat16*)pw6);
    pack_dcn<<<dim3(180), blk>>>(w_dcn,  (__nv_bfloat16*)pd1);
    pack_dcn<<<dim3(180), blk>>>(w_cdcn, (__nv_bfloat16*)pd2);

    // ---- first alignment stage ----
    tconv_k<64, 64, 2><<<gC, blk, SM64>>>(nbrT, refT, (__nv_bfloat16*)pw1, b_off1, bufA, 1);
    tconv_k<64, 64, 1><<<gC, blk, SM64>>>(bufA, nullptr, (__nv_bfloat16*)pw2, b_off2, bufB, 1);
    tconv_k<72, 80, 1><<<gC3, blk, SM80>>>(bufB, nullptr, (__nv_bfloat16*)pw3, b_co, bufCO, 0);
    dcnw_k<<<gD, blk, SMD>>>(nbrT, bufCO, (__nv_bfloat16*)pd1, b_dcn, nullptr, featT, 1);

    // ---- cascade stage ----
    tconv_k<64, 64, 2><<<gC, blk, SM64>>>(featT, refT, (__nv_bfloat16*)pw4, b_coff1, bufA, 1);
    tconv_k<64, 64, 1><<<gC, blk, SM64>>>(bufA, nullptr, (__nv_bfloat16*)pw5, b_coff2, bufB, 1);
    tconv_k<72, 80, 1><<<gC3, blk, SM80>>>(bufB, nullptr, (__nv_bfloat16*)pw6, b_cco, bufCO, 0);
    dcnw_k<<<gD, blk, SMD>>>(featT, bufCO, (__nv_bfloat16*)pd2, b_cdcn, outp, nullptr, 1);
}

// round 17
// speedup vs baseline: 1.8064x; 1.1038x over previous
#include <cuda_runtime.h>
#include <cuda_bf16.h>
#include <cstdint>

// Problem constants (fixed shapes)
#define B_  4
#define H_  160
#define W_  160
#define HW_ (H_ * W_)
#define OC_ 216   // 3 * DG * KK
#define DG_ 8
#define KK_ 9
#define SLOPE_ 0.1f

// ---------------------------------------------------------------------------
// Helpers
// ---------------------------------------------------------------------------
__device__ __forceinline__ void cp16(uint32_t s, const void* g) {
    asm volatile("cp.async.cg.shared.global [%0], [%1], 16;" :: "r"(s), "l"(g));
}
__device__ __forceinline__ void cp16z(uint32_t s, const void* g, bool ok) {
    asm volatile("cp.async.cg.shared.global [%0], [%1], 16, %2;"
                 :: "r"(s), "l"(g), "r"(ok ? 16 : 0));
}
#define CP_COMMIT() asm volatile("cp.async.commit_group;")
#define CP_WAIT0()  asm volatile("cp.async.wait_group 0;" ::: "memory")
#define CP_WAIT1()  asm volatile("cp.async.wait_group 1;" ::: "memory")

// ldmatrix / mma.sync (sm_80-level PTX; safe for plain sm_103 target)
__device__ __forceinline__ void ldsm4(uint32_t addr, uint32_t& r0, uint32_t& r1,
                                      uint32_t& r2, uint32_t& r3) {
    asm volatile("ldmatrix.sync.aligned.m8n8.x4.shared.b16 {%0,%1,%2,%3}, [%4];"
                 : "=r"(r0), "=r"(r1), "=r"(r2), "=r"(r3) : "r"(addr));
}
__device__ __forceinline__ void ldsm2t(uint32_t addr, uint32_t& r0, uint32_t& r1) {
    asm volatile("ldmatrix.sync.aligned.m8n8.x2.trans.shared.b16 {%0,%1}, [%2];"
                 : "=r"(r0), "=r"(r1) : "r"(addr));
}
__device__ __forceinline__ void mma16816(float* d, uint32_t a0, uint32_t a1,
                                         uint32_t a2, uint32_t a3,
                                         uint32_t b0, uint32_t b1) {
    asm volatile("mma.sync.aligned.m16n8k16.row.col.f32.bf16.bf16.f32 "
                 "{%0,%1,%2,%3}, {%4,%5,%6,%7}, {%8,%9}, {%0,%1,%2,%3};"
                 : "+f"(d[0]), "+f"(d[1]), "+f"(d[2]), "+f"(d[3])
                 : "r"(a0), "r"(a1), "r"(a2), "r"(a3), "r"(b0), "r"(b1));
}

// ---------------------------------------------------------------------------
// Scratch buffers (static device globals; no runtime allocation allowed)
// ---------------------------------------------------------------------------
__device__ float g_nbrT [B_ * HW_ * 64];   // NHWC fp32 (dcn1 gather)
__device__ float g_featT[B_ * HW_ * 64];   // NHWC fp32 (dcn2 gather)
__device__ float g_co   [B_ * OC_ * HW_];  // NCHW offsets/masks

// bf16 hi/lo activation planes (NHWC) for conv inputs
__device__ __nv_bfloat16 g_nbrH [B_ * HW_ * 64];
__device__ __nv_bfloat16 g_nbrL [B_ * HW_ * 64];
__device__ __nv_bfloat16 g_refH [B_ * HW_ * 64];
__device__ __nv_bfloat16 g_refL [B_ * HW_ * 64];
__device__ __nv_bfloat16 g_bufAH[B_ * HW_ * 64];
__device__ __nv_bfloat16 g_bufAL[B_ * HW_ * 64];
__device__ __nv_bfloat16 g_bufBH[B_ * HW_ * 64];
__device__ __nv_bfloat16 g_bufBL[B_ * HW_ * 64];
__device__ __nv_bfloat16 g_featH[B_ * HW_ * 64];
__device__ __nv_bfloat16 g_featL[B_ * HW_ * 64];

// packed bf16 hi/lo weight blobs: [slice][half][tap][{hi,lo}][k=64][NPs]
__device__ __nv_bfloat16 g_wb1[2 * 9 * 2 * 64 * 72];       // conv1 (2 halves)
__device__ __nv_bfloat16 g_wb2[9 * 2 * 64 * 72];           // conv2
__device__ __nv_bfloat16 g_wb3[3 * 9 * 2 * 64 * 88];       // co (3 slices, NP=80)
__device__ __nv_bfloat16 g_wb4[2 * 9 * 2 * 64 * 72];
__device__ __nv_bfloat16 g_wb5[9 * 2 * 64 * 72];
__device__ __nv_bfloat16 g_wb6[3 * 9 * 2 * 64 * 88];

// packed dcn weight blobs: [g][{hi,lo}][k'=80][n=72]  (k' = tap*8 + c)
#define DBG_ (80 * 72)
__device__ __nv_bfloat16 g_wd1[DG_ * 2 * DBG_];
__device__ __nv_bfloat16 g_wd2[DG_ * 2 * DBG_];

// ---------------------------------------------------------------------------
// NCHW -> NHWC transpose, emitting optional fp32 + bf16 hi/lo planes
// ---------------------------------------------------------------------------
__global__ __launch_bounds__(256)
void t_k(const float* __restrict__ in, float* __restrict__ outF,
         __nv_bfloat16* __restrict__ outH, __nv_bfloat16* __restrict__ outL)
{
    __shared__ float s[64][65];
    const int tid = threadIdx.x;
    const int b = blockIdx.y;
    const int p0 = blockIdx.x * 64;
#pragma unroll 1
    for (int i = tid; i < 64 * 64; i += 256) {
        const int c = i >> 6, p = i & 63;
        s[c][p] = in[((size_t)b * 64 + c) * HW_ + p0 + p];
    }
    __syncthreads();
#pragma unroll 1
    for (int i = tid; i < 64 * 64; i += 256) {
        const int p = i >> 6, c = i & 63;
        const float v = s[c][p];
        const size_t o = ((size_t)b * HW_ + p0 + p) * 64 + c;
        if (outF) outF[o] = v;
        if (outH) {
            const __nv_bfloat16 hi = __float2bfloat16(v);
            outH[o] = hi;
            outL[o] = __float2bfloat16(v - __bfloat162float(hi));
        }
    }
}

// ---------------------------------------------------------------------------
// Conv weight packing (unchanged)
// ---------------------------------------------------------------------------
__global__ __launch_bounds__(256)
void pack_k(const float* __restrict__ w, int cin_total, int nout, int np,
            int nps, int halves, __nv_bfloat16* __restrict__ blob)
{
    const int slice = blockIdx.y;
    const int cout0 = slice * nout;
    const int taphalf = 64 * nps;
    const int tapsz = 2 * taphalf;
    const int slice_stride = halves * 9 * tapsz;
    const int total = halves * 9 * 64 * np;
#pragma unroll 1
    for (int i = blockIdx.x * 256 + threadIdx.x; i < total; i += gridDim.x * 256) {
        const int n = i % np;
        const int k = (i / np) & 63;
        const int t = (i / (np * 64)) % 9;
        const int h = i / (np * 64 * 9);
        float x = 0.f;
        if (n < nout)
            x = w[((size_t)(cout0 + n) * cin_total + h * 64 + k) * 9 + t];
        const __nv_bfloat16 hi = __float2bfloat16(x);
        const __nv_bfloat16 lo = __float2bfloat16(x - __bfloat162float(hi));
        __nv_bfloat16* dst = blob + (size_t)slice * slice_stride
                             + (h * 9 + t) * tapsz + k * nps + n;
        dst[0] = hi;
        dst[taphalf] = lo;
    }
}

// ---------------------------------------------------------------------------
// DCN weight packing (unchanged)
// ---------------------------------------------------------------------------
__global__ __launch_bounds__(256)
void pack_dcn(const float* __restrict__ w, __nv_bfloat16* __restrict__ blob)
{
    const int total = DG_ * 80 * 72;
#pragma unroll 1
    for (int i = blockIdx.x * 256 + threadIdx.x; i < total; i += gridDim.x * 256) {
        const int n = i % 72;
        const int k = (i / 72) % 80;
        const int g = i / (72 * 80);
        float x = 0.f;
        if (n < 64 && k < 72)
            x = w[((size_t)n * 64 + g * 8 + (k & 7)) * 9 + (k >> 3)];
        const __nv_bfloat16 hi = __float2bfloat16(x);
        const __nv_bfloat16 lo = __float2bfloat16(x - __bfloat162float(hi));
        blob[(size_t)g * 2 * DBG_ + k * 72 + n]        = hi;
        blob[(size_t)g * 2 * DBG_ + DBG_ + k * 72 + n] = lo;
    }
}

// ---------------------------------------------------------------------------
// conv3x3: ldmatrix + mma.sync (R16 winner), A staged via cp.async from
// pre-decomposed bf16 hi/lo NHWC planes (no per-CTA conversion work).
// NOUT==64 -> emits bf16 hi/lo NHWC planes; NOUT==72 -> fp32 NCHW slice.
// ---------------------------------------------------------------------------
template <int NOUT, int NP, int HALVES>
__global__ __launch_bounds__(256, 2)
void tconv_k(const __nv_bfloat16* __restrict__ in0H, const __nv_bfloat16* __restrict__ in0L,
             const __nv_bfloat16* __restrict__ in1H, const __nv_bfloat16* __restrict__ in1L,
             const __nv_bfloat16* __restrict__ blob, const float* __restrict__ bias,
             __nv_bfloat16* __restrict__ outH, __nv_bfloat16* __restrict__ outL,
             float* __restrict__ outF, int act)
{
    constexpr int NPs     = NP + 8;
    constexpr int NT8     = NOUT / 8;           // 8 (N=64) or 9 (N=72)
    constexpr int TAPHALF = 64 * NPs;
    constexpr int TAPSZ   = 2 * TAPHALF;
    constexpr int B_BYTES = TAPSZ * 2;
    constexpr int A_OFF   = B_BYTES;
    constexpr int A_BYTES = 180 * 72 * 2;
    constexpr int NSLICE  = (NOUT == 72) ? 3 : 1;
    constexpr int LDO     = NP + 4;

    extern __shared__ uint8_t sm[];
    const uint32_t smb = (uint32_t)__cvta_generic_to_shared(sm);
    const uint32_t smbAhi = smb + A_OFF;
    const uint32_t smbAlo = smbAhi + A_BYTES;

    const int tid  = threadIdx.x;
    const int w    = tid >> 5;
    const int lane = tid & 31;
    const int slice = blockIdx.z % NSLICE;
    const int b     = blockIdx.z / NSLICE;
    const int by = blockIdx.y * 8;
    const int bx = blockIdx.x * 16;

    float acc[NT8][4];
#pragma unroll
    for (int nt = 0; nt < NT8; ++nt)
#pragma unroll
        for (int q = 0; q < 4; ++q) acc[nt][q] = 0.f;

    const __nv_bfloat16* bl = blob + (size_t)slice * (HALVES * 9 * TAPSZ);

#pragma unroll 1
    for (int h = 0; h < HALVES; ++h) {
        __syncthreads();   // previous half fully consumed before A restage

        // ---- stage A via cp.async from hi/lo planes (halo 10x18) ----
        const __nv_bfloat16* sH =
            ((HALVES == 2 && h == 1) ? in1H : in0H) + (size_t)b * HW_ * 64;
        const __nv_bfloat16* sL =
            ((HALVES == 2 && h == 1) ? in1L : in0L) + (size_t)b * HW_ * 64;
#pragma unroll 1
        for (int i = tid; i < 180 * 8; i += 256) {
            const int pix = i >> 3;        // pr*18 + pc (10 rows x 18 cols)
            const int c8  = i & 7;         // 8-channel chunk
            const int pr  = pix / 18, pc = pix - pr * 18;
            const int gy = by + pr - 1, gx = bx + pc - 1;
            const bool ok = (gy >= 0 && gy < H_ && gx >= 0 && gx < W_);
            const int gyc = ok ? gy : 0, gxc = ok ? gx : 0;
            const size_t go = ((size_t)(gyc * W_ + gxc) * 64 + c8 * 8) * 2;
            const uint32_t so = (uint32_t)((pix * 72 + c8 * 8) * 2);
            cp16z(smbAhi + so, (const uint8_t*)sH + go, ok);
            cp16z(smbAlo + so, (const uint8_t*)sL + go, ok);
        }

#pragma unroll 1
        for (int t = 0; t < 9; ++t) {
            __syncthreads();
            const __nv_bfloat16* bsrc = bl + (size_t)(h * 9 + t) * TAPSZ;
#pragma unroll 1
            for (int i = tid * 16; i < B_BYTES; i += 256 * 16)
                cp16(smb + i, (const uint8_t*)bsrc + i);
            CP_COMMIT();
            CP_WAIT0();      // waits B tap copy AND (at t==0) the A staging
            __syncthreads();

            const int ky = t / 3, kx = t - ky * 3;
            const int abase = ((w + ky) * 18 + kx) * 72;
            const uint32_t aoff = (uint32_t)((abase + (lane & 15) * 72) * 2)
                                  + (uint32_t)((lane >> 4) * 16);

#pragma unroll
            for (int kc = 0; kc < 4; ++kc) {
                uint32_t ah0, ah1, ah2, ah3, al0, al1, al2, al3;
                ldsm4(smbAhi + aoff + kc * 32, ah0, ah1, ah2, ah3);
                ldsm4(smbAlo + aoff + kc * 32, al0, al1, al2, al3);
                const uint32_t brow = smb +
                    (uint32_t)(((kc * 16 + (lane & 15)) * NPs) * 2);
#pragma unroll
                for (int nt = 0; nt < NT8; ++nt) {
                    uint32_t bh0, bh1, bl0, bl1;
                    ldsm2t(brow + nt * 16, bh0, bh1);
                    mma16816(acc[nt], ah0, ah1, ah2, ah3, bh0, bh1);
                    mma16816(acc[nt], al0, al1, al2, al3, bh0, bh1);
                    ldsm2t(brow + TAPHALF * 2 + nt * 16, bl0, bl1);
                    mma16816(acc[nt], ah0, ah1, ah2, ah3, bl0, bl1);
                }
            }
        }
    }

    // ---- epilogue: acc regs -> smem -> bias/act -> gmem ----
    __syncthreads();
    float* smf = (float*)(sm + A_OFF);
    {
        const int r0 = lane >> 2;
        const int c0 = (lane & 3) * 2;
#pragma unroll
        for (int nt = 0; nt < NT8; ++nt) {
            float* d = smf + (w * 16 + r0) * LDO + nt * 8 + c0;
            d[0] = acc[nt][0];
            d[1] = acc[nt][1];
            d += 8 * LDO;
            d[0] = acc[nt][2];
            d[1] = acc[nt][3];
        }
    }
    __syncthreads();

    if (NOUT == 64) {
#pragma unroll 1
        for (int i = tid; i < 128 * 8; i += 256) {
            const int c8 = i & 7;
            const int p  = i >> 3;
            float v[8];
            *(float4*)(v)     = *(float4*)(smf + p * LDO + 8 * c8);
            *(float4*)(v + 4) = *(float4*)(smf + p * LDO + 8 * c8 + 4);
            __nv_bfloat16 hb[8], lb[8];
#pragma unroll
            for (int j = 0; j < 8; ++j) {
                float x = v[j] + bias[8 * c8 + j];
                if (act) x = (x > 0.f) ? x : SLOPE_ * x;
                hb[j] = __float2bfloat16(x);
                lb[j] = __float2bfloat16(x - __bfloat162float(hb[j]));
            }
            const int py = by + (p >> 4);
            const int px = bx + (p & 15);
            const size_t o = ((size_t)b * HW_ + py * W_ + px) * 64 + 8 * c8;
            *(uint4*)(outH + o) = *(const uint4*)hb;
            *(uint4*)(outL + o) = *(const uint4*)lb;
        }
    } else {
        const float* bs = bias + slice * NOUT;
#pragma unroll 1
        for (int i = tid; i < NOUT * 128; i += 256) {
            const int c = i >> 7;
            const int p = i & 127;
            float v = smf[p * LDO + c] + bs[c];
            if (act) v = (v > 0.f) ? v : SLOPE_ * v;
            const int py = by + (p >> 4);
            const int px = bx + (p & 15);
            outF[((size_t)b * OC_ + slice * NOUT + c) * HW_ + py * W_ + px] = v;
        }
    }
}

// ---------------------------------------------------------------------------
// DCN with ldmatrix + mma.sync contraction (R16 winner).
// Epilogue emits: optional fp32 NCHW (final output), optional fp32 NHWC +
// bf16 hi/lo planes (intermediate feat for dcn2 gather + cascade convs).
// ---------------------------------------------------------------------------
__global__ __launch_bounds__(256, 2)
void dcnw_k(const float* __restrict__ xT, const float* __restrict__ co,
            const __nv_bfloat16* __restrict__ wblob,
            const float* __restrict__ bias,
            float* __restrict__ out, float* __restrict__ outT,
            __nv_bfloat16* __restrict__ outH, __nv_bfloat16* __restrict__ outL,
            int act)
{
    constexpr int CH_B  = 2 * DBG_ * 2;       // bytes per group chunk (hi+lo)
    constexpr int A_OFF = 2 * CH_B;           // ring of 2
    constexpr int A_ELE = 128 * 88;

    extern __shared__ uint8_t sm[];
    __nv_bfloat16* aHi = (__nv_bfloat16*)(sm + A_OFF);
    __nv_bfloat16* aLo = aHi + A_ELE;
    const uint32_t smb = (uint32_t)__cvta_generic_to_shared(sm);
    const uint32_t smbAhi = smb + A_OFF;
    const uint32_t smbAlo = smbAhi + A_ELE * 2;

    const int tid = threadIdx.x;
    const int w   = tid >> 5;
    const int lane = tid & 31;
    const int b   = blockIdx.z;
    const int by  = blockIdx.y * 8;
    const int bx  = blockIdx.x * 16;

    const float* cob = co + (size_t)b * OC_ * HW_;
    const float* xb  = xT + (size_t)b * HW_ * 64;

    // zero K-pad columns (72..79) once
    {
        const int row = tid & 127;
        __nv_bfloat16* dst = ((tid < 128) ? aHi : aLo) + row * 88 + 72;
        *(uint4*)dst = make_uint4(0, 0, 0, 0);
    }

    float acc[8][4];
#pragma unroll
    for (int nt = 0; nt < 8; ++nt)
#pragma unroll
        for (int q = 0; q < 4; ++q) acc[nt][q] = 0.f;

    auto prefetchB = [&](int g) {
        const uint8_t* src = (const uint8_t*)(wblob + (size_t)g * 2 * DBG_);
        const uint32_t dst = smb + (uint32_t)((g & 1) * CH_B);
#pragma unroll 1
        for (int i = tid * 16; i < CH_B; i += 256 * 16)
            cp16(dst + i, src + i);
    };
    prefetchB(0); CP_COMMIT();

#pragma unroll 1
    for (int g = 0; g < DG_; ++g) {
        __syncthreads();
        if (g + 1 < DG_) prefetchB(g + 1);
        CP_COMMIT();

        // ---- gather A panel for group g ----
#pragma unroll 1
        for (int i = tid; i < 128 * 9; i += 256) {
            const int px = i & 127;
            const int k  = i >> 7;
            const int y = by + (px >> 4);
            const int x = bx + (px & 15);
            const int pix = y * W_ + x;

            const float offy = cob[(size_t)(g * 18 + 2 * k    ) * HW_ + pix];
            const float offx = cob[(size_t)(g * 18 + 2 * k + 1) * HW_ + pix];
            const float ml   = cob[(size_t)(144 + g * 9 + k   ) * HW_ + pix];
            const float m    = 1.f / (1.f + __expf(-ml));

            const float py = (float)y + (float)(k / 3 - 1) + offy;
            const float pxf = (float)x + (float)(k % 3 - 1) + offx;
            const float y0f = floorf(py), x0f = floorf(pxf);
            const float ly = py - y0f,  lx = pxf - x0f;
            const int y0 = (int)y0f,    x0 = (int)x0f;

            const float w00 = (1.f - ly) * (1.f - lx) * m;
            const float w01 = (1.f - ly) * lx * m;
            const float w10 = ly * (1.f - lx) * m;
            const float w11 = ly * lx * m;

            const bool iy0 = (y0 >= 0)     && (y0 < H_);
            const bool iy1 = (y0 + 1 >= 0) && (y0 + 1 < H_);
            const bool ix0 = (x0 >= 0)     && (x0 < W_);
            const bool ix1 = (x0 + 1 >= 0) && (x0 + 1 < W_);

            float4 c00a = {0,0,0,0}, c00b = {0,0,0,0};
            float4 c01a = {0,0,0,0}, c01b = {0,0,0,0};
            float4 c10a = {0,0,0,0}, c10b = {0,0,0,0};
            float4 c11a = {0,0,0,0}, c11b = {0,0,0,0};
            if (iy0 && ix0) {
                const float4* p = (const float4*)(xb + ((size_t)(y0 * W_ + x0)) * 64 + g * 8);
                c00a = __ldg(p); c00b = __ldg(p + 1);
            }
            if (iy0 && ix1) {
                const float4* p = (const float4*)(xb + ((size_t)(y0 * W_ + x0 + 1)) * 64 + g * 8);
                c01a = __ldg(p); c01b = __ldg(p + 1);
            }
            if (iy1 && ix0) {
                const float4* p = (const float4*)(xb + ((size_t)((y0 + 1) * W_ + x0)) * 64 + g * 8);
                c10a = __ldg(p); c10b = __ldg(p + 1);
            }
            if (iy1 && ix1) {
                const float4* p = (const float4*)(xb + ((size_t)((y0 + 1) * W_ + x0 + 1)) * 64 + g * 8);
                c11a = __ldg(p); c11b = __ldg(p + 1);
            }

            float s[8];
            s[0] = w00*c00a.x + w01*c01a.x + w10*c10a.x + w11*c11a.x;
            s[1] = w00*c00a.y + w01*c01a.y + w10*c10a.y + w11*c11a.y;
            s[2] = w00*c00a.z + w01*c01a.z + w10*c10a.z + w11*c11a.z;
            s[3] = w00*c00a.w + w01*c01a.w + w10*c10a.w + w11*c11a.w;
            s[4] = w00*c00b.x + w01*c01b.x + w10*c10b.x + w11*c11b.x;
            s[5] = w00*c00b.y + w01*c01b.y + w10*c10b.y + w11*c11b.y;
            s[6] = w00*c00b.z + w01*c01b.z + w10*c10b.z + w11*c11b.z;
            s[7] = w00*c00b.w + w01*c01b.w + w10*c10b.w + w11*c11b.w;

            __nv_bfloat16 hi8[8], lo8[8];
#pragma unroll
            for (int c = 0; c < 8; ++c) {
                hi8[c] = __float2bfloat16(s[c]);
                lo8[c] = __float2bfloat16(s[c] - __bfloat162float(hi8[c]));
            }
            *(uint4*)(aHi + px * 88 + k * 8) = *(const uint4*)hi8;
            *(uint4*)(aLo + px * 88 + k * 8) = *(const uint4*)lo8;
        }

        CP_WAIT1();
        __syncthreads();

        // ---- mma contraction for group g ----
        const uint32_t bBase = smb + (uint32_t)((g & 1) * CH_B);
        const uint32_t aoff = (uint32_t)(((w * 16 + (lane & 15)) * 88) * 2)
                              + (uint32_t)((lane >> 4) * 16);
#pragma unroll
        for (int kt = 0; kt < 5; ++kt) {
            uint32_t ah0, ah1, ah2, ah3, al0, al1, al2, al3;
            ldsm4(smbAhi + aoff + kt * 32, ah0, ah1, ah2, ah3);
            ldsm4(smbAlo + aoff + kt * 32, al0, al1, al2, al3);
            const uint32_t brow = bBase +
                (uint32_t)(((kt * 16 + (lane & 15)) * 72) * 2);
#pragma unroll
            for (int nt = 0; nt < 8; ++nt) {
                uint32_t bh0, bh1, bl0, bl1;
                ldsm2t(brow + nt * 16, bh0, bh1);
                mma16816(acc[nt], ah0, ah1, ah2, ah3, bh0, bh1);
                mma16816(acc[nt], al0, al1, al2, al3, bh0, bh1);
                ldsm2t(brow + DBG_ * 2 + nt * 16, bl0, bl1);
                mma16816(acc[nt], ah0, ah1, ah2, ah3, bl0, bl1);
            }
        }
    }

    // ---- epilogue ----
    __syncthreads();
    float* smf = (float*)(sm + A_OFF);   // 128 x 68 fp32
    {
        const int r0 = lane >> 2;
        const int c0 = (lane & 3) * 2;
#pragma unroll
        for (int nt = 0; nt < 8; ++nt) {
            float* d = smf + (w * 16 + r0) * 68 + nt * 8 + c0;
            d[0] = acc[nt][0];
            d[1] = acc[nt][1];
            d += 8 * 68;
            d[0] = acc[nt][2];
            d[1] = acc[nt][3];
        }
    }
    __syncthreads();

    if (out) {
#pragma unroll 1
        for (int i = tid; i < 64 * 128; i += 256) {
            const int c = i >> 7;
            const int p = i & 127;
            float v = smf[p * 68 + c] + bias[c];
            if (act) v = (v > 0.f) ? v : SLOPE_ * v;
            const int py = by + (p >> 4);
            const int px = bx + (p & 15);
            out[((size_t)b * 64 + c) * HW_ + py * W_ + px] = v;
        }
    }
    if (outT) {
#pragma unroll 1
        for (int i = tid; i < 128 * 8; i += 256) {
            const int c8 = i & 7;
            const int p  = i >> 3;
            float v[8];
            *(float4*)(v)     = *(float4*)(smf + p * 68 + 8 * c8);
            *(float4*)(v + 4) = *(float4*)(smf + p * 68 + 8 * c8 + 4);
            __nv_bfloat16 hb[8], lb[8];
#pragma unroll
            for (int j = 0; j < 8; ++j) {
                float x = v[j] + bias[8 * c8 + j];
                if (act) x = (x > 0.f) ? x : SLOPE_ * x;
                v[j] = x;
                hb[j] = __float2bfloat16(x);
                lb[j] = __float2bfloat16(x - __bfloat162float(hb[j]));
            }
            const int py = by + (p >> 4);
            const int px = bx + (p & 15);
            const size_t o = ((size_t)b * HW_ + py * W_ + px) * 64 + 8 * c8;
            *(float4*)(outT + o)     = *(float4*)(v);
            *(float4*)(outT + o + 4) = *(float4*)(v + 4);
            *(uint4*)(outH + o) = *(const uint4*)hb;
            *(uint4*)(outL + o) = *(const uint4*)lb;
        }
    }
}

// ---------------------------------------------------------------------------
// Launch
// ---------------------------------------------------------------------------
extern "C" void kernel_launch(void* const* d_in, const int* in_sizes, int n_in,
                              void* d_out, int out_size)
{
    const float* nbr     = (const float*)d_in[0];
    const float* ref     = (const float*)d_in[1];
    const float* w_off1  = (const float*)d_in[2];
    const float* b_off1  = (const float*)d_in[3];
    const float* w_off2  = (const float*)d_in[4];
    const float* b_off2  = (const float*)d_in[5];
    const float* w_co    = (const float*)d_in[6];
    const float* b_co    = (const float*)d_in[7];
    const float* w_dcn   = (const float*)d_in[8];
    const float* b_dcn   = (const float*)d_in[9];
    const float* w_coff1 = (const float*)d_in[10];
    const float* b_coff1 = (const float*)d_in[11];
    const float* w_coff2 = (const float*)d_in[12];
    const float* b_coff2 = (const float*)d_in[13];
    const float* w_cco   = (const float*)d_in[14];
    const float* b_cco   = (const float*)d_in[15];
    const float* w_cdcn  = (const float*)d_in[16];
    const float* b_cdcn  = (const float*)d_in[17];
    float* outp = (float*)d_out;

    void *pNT, *pFT, *pCO;
    void *pNH, *pNL, *pRH, *pRL, *pAH, *pAL, *pBH, *pBL, *pFH, *pFL;
    void *pw1, *pw2, *pw3, *pw4, *pw5, *pw6, *pd1, *pd2;
    cudaGetSymbolAddress(&pNT, g_nbrT);
    cudaGetSymbolAddress(&pFT, g_featT);
    cudaGetSymbolAddress(&pCO, g_co);
    cudaGetSymbolAddress(&pNH, g_nbrH);
    cudaGetSymbolAddress(&pNL, g_nbrL);
    cudaGetSymbolAddress(&pRH, g_refH);
    cudaGetSymbolAddress(&pRL, g_refL);
    cudaGetSymbolAddress(&pAH, g_bufAH);
    cudaGetSymbolAddress(&pAL, g_bufAL);
    cudaGetSymbolAddress(&pBH, g_bufBH);
    cudaGetSymbolAddress(&pBL, g_bufBL);
    cudaGetSymbolAddress(&pFH, g_featH);
    cudaGetSymbolAddress(&pFL, g_featL);
    cudaGetSymbolAddress(&pw1, g_wb1);
    cudaGetSymbolAddress(&pw2, g_wb2);
    cudaGetSymbolAddress(&pw3, g_wb3);
    cudaGetSymbolAddress(&pw4, g_wb4);
    cudaGetSymbolAddress(&pw5, g_wb5);
    cudaGetSymbolAddress(&pw6, g_wb6);
    cudaGetSymbolAddress(&pd1, g_wd1);
    cudaGetSymbolAddress(&pd2, g_wd2);
    float* nbrT  = (float*)pNT;
    float* featT = (float*)pFT;
    float* bufCO = (float*)pCO;
    __nv_bfloat16* nbrH  = (__nv_bfloat16*)pNH;
    __nv_bfloat16* nbrL  = (__nv_bfloat16*)pNL;
    __nv_bfloat16* refH  = (__nv_bfloat16*)pRH;
    __nv_bfloat16* refL  = (__nv_bfloat16*)pRL;
    __nv_bfloat16* bufAH = (__nv_bfloat16*)pAH;
    __nv_bfloat16* bufAL = (__nv_bfloat16*)pAL;
    __nv_bfloat16* bufBH = (__nv_bfloat16*)pBH;
    __nv_bfloat16* bufBL = (__nv_bfloat16*)pBL;
    __nv_bfloat16* featH = (__nv_bfloat16*)pFH;
    __nv_bfloat16* featL = (__nv_bfloat16*)pFL;

    constexpr int SM64 = 2 * 2 * 64 * 72 * 2 + 2 * 180 * 72 * 2;   // 88704
    constexpr int SM80 = 2 * 2 * 64 * 88 * 2 + 2 * 180 * 72 * 2;   // 96896
    constexpr int SMD  = 2 * (2 * DBG_ * 2) + 2 * 128 * 88 * 2;    // 91136
    cudaFuncSetAttribute(tconv_k<64, 64, 2>, cudaFuncAttributeMaxDynamicSharedMemorySize, SM64);
    cudaFuncSetAttribute(tconv_k<64, 64, 1>, cudaFuncAttributeMaxDynamicSharedMemorySize, SM64);
    cudaFuncSetAttribute(tconv_k<72, 80, 1>, cudaFuncAttributeMaxDynamicSharedMemorySize, SM80);
    cudaFuncSetAttribute(dcnw_k, cudaFuncAttributeMaxDynamicSharedMemorySize, SMD);

    const dim3 blk(256);
    const dim3 gT(HW_ / 64, B_);
    const dim3 gC(W_ / 16, H_ / 8, B_);          // (10, 20, 4)
    const dim3 gC3(W_ / 16, H_ / 8, B_ * 3);     // (10, 20, 12)
    const dim3 gD(W_ / 16, H_ / 8, B_);          // dcn: 128-px tiles

    // transposes + decomposition
    t_k<<<gT, blk>>>(nbr, nbrT, nbrH, nbrL);
    t_k<<<gT, blk>>>(ref, nullptr, refH, refL);

    // weight packing
    pack_k<<<dim3(72, 1), blk>>>(w_off1, 128, 64, 64, 72, 2, (__nv_bfloat16*)pw1);
    pack_k<<<dim3(36, 1), blk>>>(w_off2,  64, 64, 64, 72, 1, (__nv_bfloat16*)pw2);
    pack_k<<<dim3(18, 3), blk>>>(w_co,    64, 72, 80, 88, 1, (__nv_bfloat16*)pw3);
    pack_k<<<dim3(72, 1), blk>>>(w_coff1, 128, 64, 64, 72, 2, (__nv_bfloat16*)pw4);
    pack_k<<<dim3(36, 1), blk>>>(w_coff2,  64, 64, 64, 72, 1, (__nv_bfloat16*)pw5);
    pack_k<<<dim3(18, 3), blk>>>(w_cco,    64, 72, 80, 88, 1, (__nv_bfloat16*)pw6);
    pack_dcn<<<dim3(180), blk>>>(w_dcn,  (__nv_bfloat16*)pd1);
    pack_dcn<<<dim3(180), blk>>>(w_cdcn, (__nv_bfloat16*)pd2);

    // ---- first alignment stage ----
    tconv_k<64, 64, 2><<<gC, blk, SM64>>>(nbrH, nbrL, refH, refL,
        (__nv_bfloat16*)pw1, b_off1, bufAH, bufAL, nullptr, 1);
    tconv_k<64, 64, 1><<<gC, blk, SM64>>>(bufAH, bufAL, nullptr, nullptr,
        (__nv_bfloat16*)pw2, b_off2, bufBH, bufBL, nullptr, 1);
    tconv_k<72, 80, 1><<<gC3, blk, SM80>>>(bufBH, bufBL, nullptr, nullptr,
        (__nv_bfloat16*)pw3, b_co, nullptr, nullptr, bufCO, 0);
    dcnw_k<<<gD, blk, SMD>>>(nbrT, bufCO, (__nv_bfloat16*)pd1, b_dcn,
        nullptr, featT, featH, featL, 1);

    // ---- cascade stage ----
    tconv_k<64, 64, 2><<<gC, blk, SM64>>>(featH, featL, refH, refL,
        (__nv_bfloat16*)pw4, b_coff1, bufAH, bufAL, nullptr, 1);
    tconv_k<64, 64, 1><<<gC, blk, SM64>>>(bufAH, bufAL, nullptr, nullptr,
        (__nv_bfloat16*)pw5, b_coff2, bufBH, bufBL, nullptr, 1);
    tconv_k<72, 80, 1><<<gC3, blk, SM80>>>(bufBH, bufBL, nullptr, nullptr,
        (__nv_bfloat16*)pw6, b_cco, nullptr, nullptr, bufCO, 0);
    dcnw_k<<<gD, blk, SMD>>>(featT, bufCO, (__nv_bfloat16*)pd2, b_cdcn,
        outp, nullptr, nullptr, nullptr, 1);
}